// round 13
// baseline (speedup 1.0000x reference)
#include <cuda_runtime.h>
#include <cuda_fp16.h>
#include <math.h>
#include <stdint.h>

// Problem constants (B=8, C=256, H=W=128, win_n=4, shift=16)
#define HW   16384
#define IMG  128
#define NREG 29
#define TOTPIX 229376
#define COUT 448        // 256 V + 96 Pq(3 taps x 32) + 96 Pk

typedef uint32_t u32;
typedef unsigned short u16;

__device__ __forceinline__ float f16r(float v) {
    return __half2float(__float2half_rn(v));
}
__device__ __forceinline__ u32 pack2(float e0, float e1) {   // e0 -> lo half
    __half2 h = __floats2half2_rn(e0, e1);
    return *reinterpret_cast<u32*>(&h);
}

// m16n8k16 fp16 MMA, fp32 accumulate
#define MMA_F16(d, a0, a1, a2, a3, b0, b1)                                           \
    asm volatile("mma.sync.aligned.m16n8k16.row.col.f32.f16.f16.f32 "                \
                 "{%0,%1,%2,%3},{%4,%5,%6,%7},{%8,%9},{%0,%1,%2,%3};"                \
                 : "+f"(d[0]), "+f"(d[1]), "+f"(d[2]), "+f"(d[3])                    \
                 : "r"(a0), "r"(a1), "r"(a2), "r"(a3), "r"(b0), "r"(b1))

__device__ __forceinline__ void cpa16(u32 dst, const u32* src) {
    asm volatile("cp.async.cg.shared.global [%0], [%1], 16;" :: "r"(dst), "l"(src));
}
#define CPA_COMMIT asm volatile("cp.async.commit_group;")
#define CPA_WAIT1  asm volatile("cp.async.wait_group 1;")
#define CPA_WAIT0  asm volatile("cp.async.wait_all;")

// Region tables: 12 win (rows 1..3 x cols 0..3), 9 shift-inner, 8 borders
__constant__ int c_h0[NREG] = {32,32,32,32, 64,64,64,64, 96,96,96,96,
                               16,16,16, 48,48,48, 80,80,80,
                               0,0,0, 16,16, 112,112,112};
__constant__ int c_w0[NREG] = {0,32,64,96, 0,32,64,96, 0,32,64,96,
                               16,48,80, 16,48,80, 16,48,80,
                               0,16,112, 0,112, 0,16,112};
__constant__ int c_Hr[NREG] = {32,32,32,32,32,32,32,32,32,32,32,32,
                               32,32,32,32,32,32,32,32,32,
                               16,16,16, 96,96, 16,16,16};
__constant__ int c_Wr[NREG] = {32,32,32,32,32,32,32,32,32,32,32,32,
                               32,32,32,32,32,32,32,32,32,
                               16,96,16, 16,16, 16,96,16};
__constant__ int c_N[NREG]  = {1024,1024,1024,1024,1024,1024,1024,1024,1024,1024,1024,1024,
                               1024,1024,1024,1024,1024,1024,1024,1024,1024,
                               256,1536,256, 1536,1536, 256,1536,256};
__constant__ int c_base[NREG] = {0,8192,16384,24576,32768,40960,49152,57344,65536,73728,81920,90112,
                                 98304,106496,114688,122880,131072,139264,147456,155648,163840,
                                 172032,174080,186368, 188416,200704, 212992,215040,227328};

// Scratch (__device__ globals)
static __device__ u32   g_W16h[COUT * 128];                  // [co][ci-pair] fp16x2 hi
static __device__ u32   g_W16l[COUT * 128];                  // lo residual
static __device__ u32   g_X16h[(size_t)TOTPIX * 128];        // [pix][ci-pair] fp16x2 hi
static __device__ u32   g_X16l[(size_t)TOTPIX * 128];        // lo residual
static __device__ u32   g_V16 [(size_t)TOTPIX * 128];        // [tile32][ch][key-pair]
static __device__ float g_PQK[(size_t)TOTPIX * 192];
static __device__ u32   g_Q16h[(size_t)TOTPIX * 16];         // [pix][d-pair]
static __device__ u32   g_Q16l[(size_t)TOTPIX * 16];
static __device__ u32   g_K16h[(size_t)TOTPIX * 16];
static __device__ u32   g_K16l[(size_t)TOTPIX * 16];
static __device__ int   g_pix[TOTPIX];
static __device__ float g_qsc[32], g_qof[32], g_ksc[32], g_kof[32];

// ---------------------------------------------------------------- prep kernels
__device__ __forceinline__ float wall_val(const float* Wq, const float* Wk,
                                          const float* Wv, int co, int ci) {
    if (co < 256) return Wv[co * 256 + ci];
    if (co < 352) { int t = (co - 256) >> 5, c8 = (co - 256) & 31;
                    return Wq[(c8 * 256 + ci) * 3 + t]; }
    { int t = (co - 352) >> 5, c8 = (co - 352) & 31;
      return Wk[(c8 * 256 + ci) * 3 + t]; }
}

__global__ void prep_wall(const float* __restrict__ Wq, const float* __restrict__ Wk,
                          const float* __restrict__ Wv) {
    int idx = blockIdx.x * 256 + threadIdx.x;
    if (idx >= COUT * 128) return;
    int co = idx >> 7, cp = idx & 127;
    float v0 = wall_val(Wq, Wk, Wv, co, 2 * cp);
    float v1 = wall_val(Wq, Wk, Wv, co, 2 * cp + 1);
    g_W16h[idx] = pack2(v0, v1);
    g_W16l[idx] = pack2(v0 - f16r(v0), v1 - f16r(v1));
}

__global__ void prep_bn(const float* bq, const float* qs, const float* qo, const float* qm, const float* qv,
                        const float* bk, const float* ks, const float* ko, const float* km, const float* kv) {
    int c = threadIdx.x;
    if (c >= 32) return;
    float sc = qs[c] * rsqrtf(qv[c] + 1e-5f);
    g_qsc[c] = sc;
    g_qof[c] = bq[c] * sc + qo[c] - qm[c] * sc;
    sc = ks[c] * rsqrtf(kv[c] + 1e-5f);
    g_ksc[c] = sc;
    g_kof[c] = bk[c] * sc + ko[c] - km[c] * sc;
}

__global__ void prep_pix() {
    int inst = blockIdx.y;
    int region = inst >> 3, b = inst & 7;
    int N = c_N[region];
    int n = blockIdx.x * 256 + threadIdx.x;
    if (n >= N) return;
    int Wr = c_Wr[region];
    int h = n / Wr, w = n - h * Wr;
    g_pix[c_base[region] + b * N + n] = b * (256 * HW) + (c_h0[region] + h) * IMG + c_w0[region] + w;
}

// ---------------- x_pack: one-time transpose-gather of x into fp16 hi/lo
// [pix][ci-pair] layout. Block: 32 pixels x 256 channels.
__global__ __launch_bounds__(256) void x_pack(const float* __restrict__ x) {
    __shared__ u16 Xh[256 * 33];
    __shared__ u16 Xl[256 * 33];
    __shared__ int pas[32];
    int tid = threadIdx.x;
    int pixbase = blockIdx.x * 32;
    if (tid < 32) pas[tid] = g_pix[pixbase + tid];
    __syncthreads();
    int m = tid & 31, cw = tid >> 5;
#pragma unroll
    for (int r = 0; r < 32; r++) {
        int ci = cw + r * 8;
        float v = x[pas[m] + ci * HW];
        float h = f16r(v);
        Xh[ci * 33 + m] = __half_as_ushort(__float2half_rn(v));
        Xl[ci * 33 + m] = __half_as_ushort(__float2half_rn(v - h));
    }
    __syncthreads();
#pragma unroll
    for (int r = 0; r < 16; r++) {
        int idx = tid + r * 256;
        int mm = idx >> 7, cp = idx & 127;
        size_t o = (size_t)(pixbase + mm) * 128 + cp;
        g_X16h[o] = (u32)Xh[(2 * cp) * 33 + mm] | ((u32)Xh[(2 * cp + 1) * 33 + mm] << 16);
        g_X16l[o] = (u32)Xl[(2 * cp) * 33 + mm] | ((u32)Xl[(2 * cp + 1) * 33 + mm] << 16);
    }
}

// ---------------- QKV GEMM: [pix,256]@[256,448]
// A loaded as pre-packed fp16 float4s (x_pack). V-column tiles (n0<256): plain
// fp16, packed-layout output. Q/K tap tiles: split-fp16 x3.
__global__ __launch_bounds__(256) void qkv_gemm(const float* __restrict__ bv) {
    int inst = blockIdx.z;
    int region = inst >> 3, b = inst & 7;
    int N = c_N[region];
    int m0 = blockIdx.y * 64;
    if (m0 >= N) return;
    int pb = c_base[region] + b * N;
    int n0 = blockIdx.x * 64;
    bool vt = (n0 < 256);          // pure-V tile: plain fp16

    __shared__ __align__(16) u32 Ah[64 * 20], Al[64 * 20];
    __shared__ __align__(16) u32 Bh[64 * 20], Bl[64 * 20];
    __shared__ u16 Vs16[64 * 66];  // [ch-local][pix-local] staging for packed V

    int tid = threadIdx.x;
    int lane = tid & 31, w = tid >> 5;
    int g = lane >> 2, t = lane & 3;
    int mt = w & 3, ntq = w >> 2;

    float acc[4][4];
#pragma unroll
    for (int i = 0; i < 4; i++)
#pragma unroll
        for (int j = 0; j < 4; j++) acc[i][j] = 0.f;

    for (int k0 = 0; k0 < 256; k0 += 32) {
        __syncthreads();
        {   // A: 64 m x 16 k-pairs, one float4 per thread
            int m = tid >> 2, c4 = tid & 3;
            size_t src = (size_t)(pb + m0 + m) * 128 + k0 / 2 + c4 * 4;
            *(float4*)&Ah[m * 20 + c4 * 4] = *(const float4*)&g_X16h[src];
            if (!vt) *(float4*)&Al[m * 20 + c4 * 4] = *(const float4*)&g_X16l[src];
        }
        {   // B: 64 n x 16 k-pairs
            int n = tid >> 2, c4 = tid & 3;
            *(float4*)&Bh[n * 20 + c4 * 4] = *(const float4*)&g_W16h[(size_t)(n0 + n) * 128 + k0 / 2 + c4 * 4];
            if (!vt)
                *(float4*)&Bl[n * 20 + c4 * 4] = *(const float4*)&g_W16l[(size_t)(n0 + n) * 128 + k0 / 2 + c4 * 4];
        }
        __syncthreads();
#pragma unroll
        for (int kt = 0; kt < 2; kt++) {
            int ar = (mt * 16 + g) * 20 + kt * 8 + t;
            u32 ah0 = Ah[ar], ah1 = Ah[ar + 160], ah2 = Ah[ar + 4], ah3 = Ah[ar + 164];
#pragma unroll
            for (int ns = 0; ns < 4; ns++) {
                int nr = (ntq * 32 + ns * 8 + g) * 20 + kt * 8 + t;
                u32 bh0 = Bh[nr], bh1 = Bh[nr + 4];
                MMA_F16(acc[ns], ah0, ah1, ah2, ah3, bh0, bh1);
                if (!vt) {
                    u32 al0 = Al[ar], al1 = Al[ar + 160], al2 = Al[ar + 4], al3 = Al[ar + 164];
                    u32 bl0 = Bl[nr], bl1 = Bl[nr + 4];
                    MMA_F16(acc[ns], al0, al1, al2, al3, bh0, bh1);
                    MMA_F16(acc[ns], ah0, ah1, ah2, ah3, bl0, bl1);
                }
            }
        }
    }
    if (vt) {
        // stage V outputs (with bias) into [ch-local][pix-local] fp16 smem
        int r0 = mt * 16 + g, r8 = r0 + 8;
#pragma unroll
        for (int ns = 0; ns < 4; ns++) {
            int co = n0 + ntq * 32 + ns * 8 + 2 * t;
            int chl = co - n0;
            float b0 = bv[co], b1 = bv[co + 1];
            Vs16[chl * 66 + r0]       = __half_as_ushort(__float2half_rn(acc[ns][0] + b0));
            Vs16[(chl + 1) * 66 + r0] = __half_as_ushort(__float2half_rn(acc[ns][1] + b1));
            Vs16[chl * 66 + r8]       = __half_as_ushort(__float2half_rn(acc[ns][2] + b0));
            Vs16[(chl + 1) * 66 + r8] = __half_as_ushort(__float2half_rn(acc[ns][3] + b1));
        }
        __syncthreads();
        // cooperative write in packed layout: 64 ch x 32 key-pairs = 2048 u32
        int tile0 = (pb + m0) >> 5;
#pragma unroll
        for (int r = 0; r < 8; r++) {
            int idx = tid + r * 256;
            int chl = idx >> 5, kpl = idx & 31;        // kpl: pix-pair 0..31
            u32 v = (u32)Vs16[chl * 66 + 2 * kpl] | ((u32)Vs16[chl * 66 + 2 * kpl + 1] << 16);
            int tileIdx = tile0 + (kpl >> 4);
            g_V16[(size_t)tileIdx * 4096 + (n0 + chl) * 16 + (kpl & 15)] = v;
        }
    } else {
#pragma unroll
        for (int ns = 0; ns < 4; ns++) {
            int co = n0 + ntq * 32 + ns * 8 + 2 * t;
            size_t mg  = (size_t)(pb + m0 + mt * 16 + g);
            size_t mg8 = mg + 8;
            int cp = co - 256;
            g_PQK[mg  * 192 + cp]     = acc[ns][0];
            g_PQK[mg  * 192 + cp + 1] = acc[ns][1];
            g_PQK[mg8 * 192 + cp]     = acc[ns][2];
            g_PQK[mg8 * 192 + cp + 1] = acc[ns][3];
        }
    }
}

// ------------- combine conv taps + BN + ReLU, split Q/K into fp16 hi/lo pairs
__global__ void combine_qk() {
    int inst = blockIdx.y;
    int region = inst >> 3, b = inst & 7;
    int N = c_N[region];
    int idx = blockIdx.x * 256 + threadIdx.x;
    int n = idx >> 4;
    if (n >= N) return;
    int cp = idx & 15, c0 = 2 * cp;
    int Wr = c_Wr[region], Hr = c_Hr[region];
    int pb = c_base[region] + b * N;
    int h = n / Wr, w = n - h * Wr;
    size_t rowp = (size_t)(pb + n) * 192;

    float2 q = *(float2*)&g_PQK[rowp + 32 + c0];
    if (w > 0)      { float2 a = *(float2*)&g_PQK[rowp - 192 + c0]; q.x += a.x; q.y += a.y; }
    if (w < Wr - 1) { float2 a = *(float2*)&g_PQK[rowp + 192 + 64 + c0]; q.x += a.x; q.y += a.y; }
    q.x = fmaxf(fmaf(q.x, g_qsc[c0], g_qof[c0]), 0.f);
    q.y = fmaxf(fmaf(q.y, g_qsc[c0 + 1], g_qof[c0 + 1]), 0.f);
    g_Q16h[(size_t)(pb + n) * 16 + cp] = pack2(q.x, q.y);
    g_Q16l[(size_t)(pb + n) * 16 + cp] = pack2(q.x - f16r(q.x), q.y - f16r(q.y));

    float2 k = *(float2*)&g_PQK[rowp + 96 + 32 + c0];
    if (h > 0)      { float2 a = *(float2*)&g_PQK[rowp - (size_t)Wr * 192 + 96 + c0]; k.x += a.x; k.y += a.y; }
    if (h < Hr - 1) { float2 a = *(float2*)&g_PQK[rowp + (size_t)Wr * 192 + 96 + 64 + c0]; k.x += a.x; k.y += a.y; }
    k.x = fmaxf(fmaf(k.x, g_ksc[c0], g_kof[c0]), 0.f);
    k.y = fmaxf(fmaf(k.y, g_ksc[c0 + 1], g_kof[c0 + 1]), 0.f);
    g_K16h[(size_t)(pb + n) * 16 + cp] = pack2(k.x, k.y);
    g_K16l[(size_t)(pb + n) * 16 + cp] = pack2(k.x - f16r(k.x), k.y - f16r(k.y));
}

// ------------------- fp16 flash attention, 64 q-rows x 64-key tiles (R9 proven)
// 256 threads, 2 CTA/SM. mode 0: out = x + delta (shift partition). mode 1: RMW.
// smem offsets in u32 units:
#define OKH 0          // 2 stages x 64x20
#define OKL 2560
#define OVS 5120       // 2 stages x 256x36
#define OP16 23552     // 64 x 36
#define OWM 25856      // wmax [2][64]
#define OWS 25984      // wsum [2][64]
#define OSTAT 26112    // rmax/rsum/rscale/pas 4x64
#define ASMEM (26368 * 4)

__global__ __launch_bounds__(256, 2) void attn(const float* __restrict__ gamma,
                                               const float* __restrict__ xin,
                                               float* __restrict__ out,
                                               int inst0, int mode) {
    extern __shared__ u32 sm32[];
    u32* Ps16 = sm32 + OP16;
    float* wmax = (float*)(sm32 + OWM);
    float* wsum = (float*)(sm32 + OWS);
    float* rmax = (float*)(sm32 + OSTAT);
    float* rsum = rmax + 64;
    float* rscale = rsum + 64;
    int* pas = (int*)(rscale + 64);
    float* stage = (float*)(sm32 + OVS);   // epilogue union over V buffers

    u32 smb = (u32)__cvta_generic_to_shared(sm32);

    int inst = inst0 + blockIdx.y;
    int region = inst >> 3, b = inst & 7;
    int N = c_N[region];
    int n0 = blockIdx.x * 64;
    if (n0 >= N) return;
    int pb = c_base[region] + b * N;

    int tid = threadIdx.x;
    int lane = tid & 31, w = tid >> 5;
    int g = lane >> 2, t = lane & 3;
    if (tid < 64) {
        rmax[tid] = -1e30f; rsum[tid] = 0.f;
        pas[tid] = g_pix[pb + n0 + tid];
    }

    int mt = w & 3, ntk = w >> 2;             // S mapping: rows mt*16, keys ntk*32
    int wm = w & 3, wslab = (w >> 2) * 128;   // PV mapping
    int rowg = mt * 16 + g;

    // Q fragments hi/lo in registers (fixed per CTA)
    u32 aqh[2][4], aql[2][4];
    {
        size_t r0 = (size_t)(pb + n0 + rowg) * 16;
        size_t r8 = r0 + 128;   // +8 rows * 16
#pragma unroll
        for (int kt = 0; kt < 2; kt++) {
            int c = kt * 8 + t;
            aqh[kt][0] = g_Q16h[r0 + c];     aqh[kt][1] = g_Q16h[r8 + c];
            aqh[kt][2] = g_Q16h[r0 + c + 4]; aqh[kt][3] = g_Q16h[r8 + c + 4];
            aql[kt][0] = g_Q16l[r0 + c];     aql[kt][1] = g_Q16l[r8 + c];
            aql[kt][2] = g_Q16l[r0 + c + 4]; aql[kt][3] = g_Q16l[r8 + c + 4];
        }
    }

    // prefetch addressing
    int kidx = tid & 127;
    const u32* ksrc = (tid < 128) ? g_K16h : g_K16l;
    u32 kdst = (tid < 128) ? (u32)OKH : (u32)OKL;

    float acc[16][4];
#pragma unroll
    for (int nt = 0; nt < 16; nt++)
#pragma unroll
        for (int r = 0; r < 4; r++) acc[nt][r] = 0.f;

    int nmt = N >> 6;
    // prologue: prefetch tile 0 into stage 0
    {
        int mb = pb;
#pragma unroll
        for (int r = 0; r < 2; r++) {
            int chunk = kidx + r * 128;
            int krow = chunk >> 2, kc4 = chunk & 3;
            cpa16(smb + (kdst + krow * 20 + kc4 * 4) * 4, &ksrc[(size_t)(mb + krow) * 16 + kc4 * 4]);
        }
        size_t vbase = (size_t)(mb >> 5) * 4096;
#pragma unroll
        for (int r = 0; r < 8; r++) {
            int idx = tid + r * 256;
            int ch = idx >> 3, sub = idx & 7;
            int half = sub >> 2, c4 = sub & 3;
            cpa16(smb + (OVS + ch * 36 + half * 16 + c4 * 4) * 4,
                  &g_V16[vbase + (size_t)half * 4096 + ch * 16 + c4 * 4]);
        }
        CPA_COMMIT;
    }

    for (int it = 0; it < nmt; it++) {
        int s = it & 1;
        __syncthreads();                       // readers of stage s^1 done
        if (it + 1 < nmt) {
            int mb = pb + (it + 1) * 64;
            int s2 = (it + 1) & 1;
#pragma unroll
            for (int r = 0; r < 2; r++) {
                int chunk = kidx + r * 128;
                int krow = chunk >> 2, kc4 = chunk & 3;
                cpa16(smb + (kdst + s2 * 1280 + krow * 20 + kc4 * 4) * 4,
                      &ksrc[(size_t)(mb + krow) * 16 + kc4 * 4]);
            }
            size_t vbase = (size_t)(mb >> 5) * 4096;
#pragma unroll
            for (int r = 0; r < 8; r++) {
                int idx = tid + r * 256;
                int ch = idx >> 3, sub = idx & 7;
                int half = sub >> 2, c4 = sub & 3;
                cpa16(smb + (OVS + s2 * 9216 + ch * 36 + half * 16 + c4 * 4) * 4,
                      &g_V16[vbase + (size_t)half * 4096 + ch * 16 + c4 * 4]);
            }
            CPA_COMMIT;
            CPA_WAIT1;
        } else {
            CPA_WAIT0;
        }
        __syncthreads();                       // tile data visible
        u32* Kh = sm32 + OKH + s * 1280;
        u32* Kl = sm32 + OKL + s * 1280;
        u32* Vs = sm32 + OVS + s * 9216;

        // ---- S: split-fp16, warp does 16 rows x 32 keys (registers)
        float sacc[4][4];
#pragma unroll
        for (int i = 0; i < 4; i++)
#pragma unroll
            for (int j = 0; j < 4; j++) sacc[i][j] = 0.f;
#pragma unroll
        for (int kt = 0; kt < 2; kt++) {
            u32 ah0 = aqh[kt][0], ah1 = aqh[kt][1], ah2 = aqh[kt][2], ah3 = aqh[kt][3];
            u32 al0 = aql[kt][0], al1 = aql[kt][1], al2 = aql[kt][2], al3 = aql[kt][3];
#pragma unroll
            for (int sub = 0; sub < 4; sub++) {
                int kr = (ntk * 32 + sub * 8 + g) * 20 + kt * 8 + t;
                u32 bh0 = Kh[kr], bh1 = Kh[kr + 4];
                u32 bl0 = Kl[kr], bl1 = Kl[kr + 4];
                MMA_F16(sacc[sub], ah0, ah1, ah2, ah3, bh0, bh1);
                MMA_F16(sacc[sub], al0, al1, al2, al3, bh0, bh1);
                MMA_F16(sacc[sub], ah0, ah1, ah2, ah3, bl0, bl1);
            }
        }
        // ---- softmax phase A: warp-local row max over 32 keys
        float m0 = fmaxf(fmaxf(sacc[0][0], sacc[0][1]), fmaxf(sacc[1][0], sacc[1][1]));
        m0 = fmaxf(m0, fmaxf(fmaxf(sacc[2][0], sacc[2][1]), fmaxf(sacc[3][0], sacc[3][1])));
        float m1 = fmaxf(fmaxf(sacc[0][2], sacc[0][3]), fmaxf(sacc[1][2], sacc[1][3]));
        m1 = fmaxf(m1, fmaxf(fmaxf(sacc[2][2], sacc[2][3]), fmaxf(sacc[3][2], sacc[3][3])));
        m0 = fmaxf(m0, __shfl_xor_sync(0xffffffffu, m0, 1));
        m0 = fmaxf(m0, __shfl_xor_sync(0xffffffffu, m0, 2));
        m1 = fmaxf(m1, __shfl_xor_sync(0xffffffffu, m1, 1));
        m1 = fmaxf(m1, __shfl_xor_sync(0xffffffffu, m1, 2));
        float rm0 = rmax[rowg], rm1 = rmax[rowg + 8];
        if (t == 0) {
            wmax[ntk * 64 + rowg]     = m0;
            wmax[ntk * 64 + rowg + 8] = m1;
        }
        __syncthreads();                       // wmax visible
        // ---- softmax phase B: exp in registers, pack to Ps16
        float nm0 = fmaxf(rm0, fmaxf(wmax[rowg], wmax[64 + rowg]));
        float nm1 = fmaxf(rm1, fmaxf(wmax[rowg + 8], wmax[64 + rowg + 8]));
        float s0 = 0.f, s1 = 0.f;
#pragma unroll
        for (int sub = 0; sub < 4; sub++) {
            float p00 = __expf(sacc[sub][0] - nm0);
            float p01 = __expf(sacc[sub][1] - nm0);
            float p10 = __expf(sacc[sub][2] - nm1);
            float p11 = __expf(sacc[sub][3] - nm1);
            s0 += p00 + p01; s1 += p10 + p11;
            int kp = ntk * 16 + sub * 4 + t;
            Ps16[rowg * 36 + kp]       = pack2(p00, p01);
            Ps16[(rowg + 8) * 36 + kp] = pack2(p10, p11);
        }
        s0 += __shfl_xor_sync(0xffffffffu, s0, 1);
        s0 += __shfl_xor_sync(0xffffffffu, s0, 2);
        s1 += __shfl_xor_sync(0xffffffffu, s1, 1);
        s1 += __shfl_xor_sync(0xffffffffu, s1, 2);
        if (t == 0) {
            wsum[ntk * 64 + rowg]     = s0;
            wsum[ntk * 64 + rowg + 8] = s1;
            if (ntk == 0) {
                rscale[rowg]     = __expf(rm0 - nm0);
                rscale[rowg + 8] = __expf(rm1 - nm1);
                rmax[rowg] = nm0; rmax[rowg + 8] = nm1;
            }
        }
        __syncthreads();                       // Ps16 + rscale + wsum visible
        // ---- PV: rescale + fp16 MMA (warp: 16 rows x 128 ch, 64 keys)
        {
            float sc0 = rscale[wm * 16 + g];
            float sc1 = rscale[wm * 16 + g + 8];
#pragma unroll
            for (int nt = 0; nt < 16; nt++) {
                acc[nt][0] *= sc0; acc[nt][1] *= sc0;
                acc[nt][2] *= sc1; acc[nt][3] *= sc1;
            }
#pragma unroll
            for (int kt = 0; kt < 4; kt++) {
                int pr = (wm * 16 + g) * 36 + kt * 8 + t;
                u32 pa0 = Ps16[pr], pa1 = Ps16[pr + 288], pa2 = Ps16[pr + 4], pa3 = Ps16[pr + 292];
#pragma unroll
                for (int nt = 0; nt < 16; nt++) {
                    int vr = (wslab + nt * 8 + g) * 36 + kt * 8 + t;
                    MMA_F16(acc[nt], pa0, pa1, pa2, pa3, Vs[vr], Vs[vr + 4]);
                }
            }
        }
        // running-sum update (rsum read only at epilogue)
        if (w < 4 && lane < 16) {
            int row = w * 16 + lane;
            rsum[row] = rsum[row] * rscale[row] + wsum[row] + wsum[64 + row];
        }
    }
    // epilogue: two passes of 32 rows staged, then coalesced write/RMW
    float gm = 0.5f * gamma[0];
#pragma unroll
    for (int pass = 0; pass < 2; pass++) {
        __syncthreads();
        if ((wm >> 1) == pass) {
            float f0 = gm / rsum[wm * 16 + g];
            float f1 = gm / rsum[wm * 16 + g + 8];
            int row0 = (wm * 16 + g) - pass * 32;
            int r0 = row0 * 264 + wslab + 2 * t;
            int r8 = (row0 + 8) * 264 + wslab + 2 * t;
#pragma unroll
            for (int nt = 0; nt < 16; nt++) {
                stage[r0 + nt * 8]     = acc[nt][0] * f0;
                stage[r0 + nt * 8 + 1] = acc[nt][1] * f0;
                stage[r8 + nt * 8]     = acc[nt][2] * f1;
                stage[r8 + nt * 8 + 1] = acc[nt][3] * f1;
            }
        }
        __syncthreads();
        int tn = tid & 7, tc = tid >> 3;
#pragma unroll
        for (int i = 0; i < 4; i++) {
            int row = tn + 8 * i;
            int pa = pas[pass * 32 + row];
#pragma unroll
            for (int j = 0; j < 8; j++) {
                int c = tc * 8 + j;
                float vv = stage[row * 264 + c];
                if (mode) out[pa + c * HW] += vv;
                else      out[pa + c * HW] = xin[pa + c * HW] + vv;
            }
        }
    }
}

// ---------------------------------------------------------------- launcher
extern "C" void kernel_launch(void* const* d_in, const int* in_sizes, int n_in,
                              void* d_out, int out_size) {
    const float* x   = (const float*)d_in[0];
    const float* Wq  = (const float*)d_in[1];
    const float* bq  = (const float*)d_in[2];
    const float* q_s = (const float*)d_in[3];
    const float* q_o = (const float*)d_in[4];
    const float* q_m = (const float*)d_in[5];
    const float* q_v = (const float*)d_in[6];
    const float* Wk  = (const float*)d_in[7];
    const float* bk  = (const float*)d_in[8];
    const float* k_s = (const float*)d_in[9];
    const float* k_o = (const float*)d_in[10];
    const float* k_m = (const float*)d_in[11];
    const float* k_v = (const float*)d_in[12];
    const float* Wv  = (const float*)d_in[13];
    const float* bv  = (const float*)d_in[14];
    const float* gam = (const float*)d_in[15];
    float* out = (float*)d_out;

    cudaFuncSetAttribute(attn, cudaFuncAttributeMaxDynamicSharedMemorySize, ASMEM);

    prep_wall<<<224, 256>>>(Wq, Wk, Wv);
    prep_bn<<<1, 32>>>(bq, q_s, q_o, q_m, q_v, bk, k_s, k_o, k_m, k_v);
    prep_pix<<<dim3(6, 232), 256>>>();
    x_pack<<<TOTPIX / 32, 256>>>(x);
    qkv_gemm<<<dim3(7, 24, 232), 256>>>(bv);
    combine_qk<<<dim3(96, 232), 256>>>();
    // shift regions (12..28) partition the image: write mode (out = x + delta)
    attn<<<dim3(24, 136), 256, ASMEM>>>(gam, x, out, 96, 0);
    // win regions (0..11): disjoint pixels within launch -> RMW
    attn<<<dim3(16, 96), 256, ASMEM>>>(gam, x, out, 0, 1);
}

// round 14
// speedup vs baseline: 1.1106x; 1.1106x over previous
#include <cuda_runtime.h>
#include <cuda_fp16.h>
#include <math.h>
#include <stdint.h>

// Problem constants (B=8, C=256, H=W=128, win_n=4, shift=16)
#define HW   16384
#define IMG  128
#define NREG 29
#define TOTPIX 229376
#define COUT 448        // 256 V + 96 Pq(3 taps x 32) + 96 Pk

typedef uint32_t u32;
typedef unsigned short u16;

__device__ __forceinline__ float f16r(float v) {
    return __half2float(__float2half_rn(v));
}
__device__ __forceinline__ u32 pack2(float e0, float e1) {   // e0 -> lo half
    __half2 h = __floats2half2_rn(e0, e1);
    return *reinterpret_cast<u32*>(&h);
}

// m16n8k16 fp16 MMA, fp32 accumulate
#define MMA_F16(d, a0, a1, a2, a3, b0, b1)                                           \
    asm volatile("mma.sync.aligned.m16n8k16.row.col.f32.f16.f16.f32 "                \
                 "{%0,%1,%2,%3},{%4,%5,%6,%7},{%8,%9},{%0,%1,%2,%3};"                \
                 : "+f"(d[0]), "+f"(d[1]), "+f"(d[2]), "+f"(d[3])                    \
                 : "r"(a0), "r"(a1), "r"(a2), "r"(a3), "r"(b0), "r"(b1))

__device__ __forceinline__ void cpa16(u32 dst, const u32* src) {
    asm volatile("cp.async.cg.shared.global [%0], [%1], 16;" :: "r"(dst), "l"(src));
}
#define CPA_COMMIT asm volatile("cp.async.commit_group;")
#define CPA_WAIT1  asm volatile("cp.async.wait_group 1;")
#define CPA_WAIT0  asm volatile("cp.async.wait_all;")

// Region tables: 12 win (rows 1..3 x cols 0..3), 9 shift-inner, 8 borders
__constant__ int c_h0[NREG] = {32,32,32,32, 64,64,64,64, 96,96,96,96,
                               16,16,16, 48,48,48, 80,80,80,
                               0,0,0, 16,16, 112,112,112};
__constant__ int c_w0[NREG] = {0,32,64,96, 0,32,64,96, 0,32,64,96,
                               16,48,80, 16,48,80, 16,48,80,
                               0,16,112, 0,112, 0,16,112};
__constant__ int c_Hr[NREG] = {32,32,32,32,32,32,32,32,32,32,32,32,
                               32,32,32,32,32,32,32,32,32,
                               16,16,16, 96,96, 16,16,16};
__constant__ int c_Wr[NREG] = {32,32,32,32,32,32,32,32,32,32,32,32,
                               32,32,32,32,32,32,32,32,32,
                               16,96,16, 16,16, 16,96,16};
__constant__ int c_N[NREG]  = {1024,1024,1024,1024,1024,1024,1024,1024,1024,1024,1024,1024,
                               1024,1024,1024,1024,1024,1024,1024,1024,1024,
                               256,1536,256, 1536,1536, 256,1536,256};
__constant__ int c_base[NREG] = {0,8192,16384,24576,32768,40960,49152,57344,65536,73728,81920,90112,
                                 98304,106496,114688,122880,131072,139264,147456,155648,163840,
                                 172032,174080,186368, 188416,200704, 212992,215040,227328};

// Scratch (__device__ globals)
static __device__ u32   g_W16h[COUT * 128];                  // [co][ci-pair] fp16x2 hi
static __device__ u32   g_W16l[COUT * 128];                  // lo residual
static __device__ u32   g_X16h[(size_t)TOTPIX * 128];        // [pix][ci-pair] fp16x2 hi
static __device__ u32   g_X16l[(size_t)TOTPIX * 128];        // lo residual
static __device__ u32   g_V16 [(size_t)TOTPIX * 128];        // [tile32][ch][key-pair]
static __device__ float g_PQK[(size_t)TOTPIX * 192];
static __device__ u32   g_Q16h[(size_t)TOTPIX * 16];         // [pix][d-pair]
static __device__ u32   g_Q16l[(size_t)TOTPIX * 16];
static __device__ u32   g_K16h[(size_t)TOTPIX * 16];
static __device__ u32   g_K16l[(size_t)TOTPIX * 16];
static __device__ int   g_pix[TOTPIX];
static __device__ float g_qsc[32], g_qof[32], g_ksc[32], g_kof[32];

// ---------------------------------------------------------------- prep kernels
__device__ __forceinline__ float wall_val(const float* Wq, const float* Wk,
                                          const float* Wv, int co, int ci) {
    if (co < 256) return Wv[co * 256 + ci];
    if (co < 352) { int t = (co - 256) >> 5, c8 = (co - 256) & 31;
                    return Wq[(c8 * 256 + ci) * 3 + t]; }
    { int t = (co - 352) >> 5, c8 = (co - 352) & 31;
      return Wk[(c8 * 256 + ci) * 3 + t]; }
}

__global__ void prep_wall(const float* __restrict__ Wq, const float* __restrict__ Wk,
                          const float* __restrict__ Wv) {
    int idx = blockIdx.x * 256 + threadIdx.x;
    if (idx >= COUT * 128) return;
    int co = idx >> 7, cp = idx & 127;
    float v0 = wall_val(Wq, Wk, Wv, co, 2 * cp);
    float v1 = wall_val(Wq, Wk, Wv, co, 2 * cp + 1);
    g_W16h[idx] = pack2(v0, v1);
    g_W16l[idx] = pack2(v0 - f16r(v0), v1 - f16r(v1));
}

__global__ void prep_bn(const float* bq, const float* qs, const float* qo, const float* qm, const float* qv,
                        const float* bk, const float* ks, const float* ko, const float* km, const float* kv) {
    int c = threadIdx.x;
    if (c >= 32) return;
    float sc = qs[c] * rsqrtf(qv[c] + 1e-5f);
    g_qsc[c] = sc;
    g_qof[c] = bq[c] * sc + qo[c] - qm[c] * sc;
    sc = ks[c] * rsqrtf(kv[c] + 1e-5f);
    g_ksc[c] = sc;
    g_kof[c] = bk[c] * sc + ko[c] - km[c] * sc;
}

__global__ void prep_pix() {
    int inst = blockIdx.y;
    int region = inst >> 3, b = inst & 7;
    int N = c_N[region];
    int n = blockIdx.x * 256 + threadIdx.x;
    if (n >= N) return;
    int Wr = c_Wr[region];
    int h = n / Wr, w = n - h * Wr;
    g_pix[c_base[region] + b * N + n] = b * (256 * HW) + (c_h0[region] + h) * IMG + c_w0[region] + w;
}

// ---------------- x_pack: one-time transpose-gather of x into fp16 hi/lo
// [pix][ci-pair] layout. Block: 32 pixels x 256 channels.
__global__ __launch_bounds__(256) void x_pack(const float* __restrict__ x) {
    __shared__ u16 Xh[256 * 33];
    __shared__ u16 Xl[256 * 33];
    __shared__ int pas[32];
    int tid = threadIdx.x;
    int pixbase = blockIdx.x * 32;
    if (tid < 32) pas[tid] = g_pix[pixbase + tid];
    __syncthreads();
    int m = tid & 31, cw = tid >> 5;
#pragma unroll
    for (int r = 0; r < 32; r++) {
        int ci = cw + r * 8;
        float v = x[pas[m] + ci * HW];
        float h = f16r(v);
        Xh[ci * 33 + m] = __half_as_ushort(__float2half_rn(v));
        Xl[ci * 33 + m] = __half_as_ushort(__float2half_rn(v - h));
    }
    __syncthreads();
#pragma unroll
    for (int r = 0; r < 16; r++) {
        int idx = tid + r * 256;
        int mm = idx >> 7, cp = idx & 127;
        size_t o = (size_t)(pixbase + mm) * 128 + cp;
        g_X16h[o] = (u32)Xh[(2 * cp) * 33 + mm] | ((u32)Xh[(2 * cp + 1) * 33 + mm] << 16);
        g_X16l[o] = (u32)Xl[(2 * cp) * 33 + mm] | ((u32)Xl[(2 * cp + 1) * 33 + mm] << 16);
    }
}

// ---------------- QKV GEMM: [pix,256]@[256,448], double-buffered cp.async
// V-column tiles (n0<256): plain fp16, packed-layout output. QK tiles: split x3.
// smem (u32 units): Ah 2x1280 | Al 2x1280 | Bh 2x1280 | Bl 2x1280 = 40KB
#define QAH 0
#define QAL 2560
#define QBH 5120
#define QBL 7680
#define QSMEM (10240 * 4)

__global__ __launch_bounds__(256) void qkv_gemm(const float* __restrict__ bv) {
    extern __shared__ u32 qsm[];
    u16* Vs16 = (u16*)qsm;         // epilogue alias (after k-loop + sync)
    u32 smb = (u32)__cvta_generic_to_shared(qsm);

    int inst = blockIdx.z;
    int region = inst >> 3, b = inst & 7;
    int N = c_N[region];
    int m0 = blockIdx.y * 64;
    if (m0 >= N) return;
    int pb = c_base[region] + b * N;
    int n0 = blockIdx.x * 64;
    bool vt = (n0 < 256);          // pure-V tile: plain fp16

    int tid = threadIdx.x;
    int lane = tid & 31, w = tid >> 5;
    int g = lane >> 2, t = lane & 3;
    int mt = w & 3, ntq = w >> 2;

    // prefetch addressing: row = tid>>2 (0..63), c4 = tid&3
    int prow = tid >> 2, pc4 = tid & 3;
    u32 sdst = (prow * 20 + pc4 * 4) * 4;   // byte offset within a stage
    size_t asrc0 = (size_t)(pb + m0 + prow) * 128 + pc4 * 4;
    size_t bsrc0 = (size_t)(n0 + prow) * 128 + pc4 * 4;

    float acc[4][4];
#pragma unroll
    for (int i = 0; i < 4; i++)
#pragma unroll
        for (int j = 0; j < 4; j++) acc[i][j] = 0.f;

    // prologue: prefetch chunk 0 into stage 0
    {
        cpa16(smb + QAH * 4 + sdst, &g_X16h[asrc0]);
        cpa16(smb + QBH * 4 + sdst, &g_W16h[bsrc0]);
        if (!vt) {
            cpa16(smb + QAL * 4 + sdst, &g_X16l[asrc0]);
            cpa16(smb + QBL * 4 + sdst, &g_W16l[bsrc0]);
        }
        CPA_COMMIT;
    }

    for (int it = 0; it < 8; it++) {         // 8 chunks of k=32
        int s = it & 1;
        __syncthreads();                     // readers of stage s^1 done
        if (it + 1 < 8) {
            int s2 = (it + 1) & 1;
            size_t ko = (size_t)(it + 1) * 16;   // k-pairs
            cpa16(smb + (QAH + s2 * 1280) * 4 + sdst, &g_X16h[asrc0 + ko]);
            cpa16(smb + (QBH + s2 * 1280) * 4 + sdst, &g_W16h[bsrc0 + ko]);
            if (!vt) {
                cpa16(smb + (QAL + s2 * 1280) * 4 + sdst, &g_X16l[asrc0 + ko]);
                cpa16(smb + (QBL + s2 * 1280) * 4 + sdst, &g_W16l[bsrc0 + ko]);
            }
            CPA_COMMIT;
            CPA_WAIT1;
        } else {
            CPA_WAIT0;
        }
        __syncthreads();                     // stage s visible
        u32* Ah = qsm + QAH + s * 1280;
        u32* Al = qsm + QAL + s * 1280;
        u32* Bh = qsm + QBH + s * 1280;
        u32* Bl = qsm + QBL + s * 1280;
#pragma unroll
        for (int kt = 0; kt < 2; kt++) {
            int ar = (mt * 16 + g) * 20 + kt * 8 + t;
            u32 ah0 = Ah[ar], ah1 = Ah[ar + 160], ah2 = Ah[ar + 4], ah3 = Ah[ar + 164];
#pragma unroll
            for (int ns = 0; ns < 4; ns++) {
                int nr = (ntq * 32 + ns * 8 + g) * 20 + kt * 8 + t;
                u32 bh0 = Bh[nr], bh1 = Bh[nr + 4];
                MMA_F16(acc[ns], ah0, ah1, ah2, ah3, bh0, bh1);
                if (!vt) {
                    u32 al0 = Al[ar], al1 = Al[ar + 160], al2 = Al[ar + 4], al3 = Al[ar + 164];
                    u32 bl0 = Bl[nr], bl1 = Bl[nr + 4];
                    MMA_F16(acc[ns], al0, al1, al2, al3, bh0, bh1);
                    MMA_F16(acc[ns], ah0, ah1, ah2, ah3, bl0, bl1);
                }
            }
        }
    }
    if (vt) {
        __syncthreads();   // all fragment reads done before aliasing stage smem
        // stage V outputs (with bias) into [ch-local][pix-local] fp16 smem
        int r0 = mt * 16 + g, r8 = r0 + 8;
#pragma unroll
        for (int ns = 0; ns < 4; ns++) {
            int co = n0 + ntq * 32 + ns * 8 + 2 * t;
            int chl = co - n0;
            float b0 = bv[co], b1 = bv[co + 1];
            Vs16[chl * 66 + r0]       = __half_as_ushort(__float2half_rn(acc[ns][0] + b0));
            Vs16[(chl + 1) * 66 + r0] = __half_as_ushort(__float2half_rn(acc[ns][1] + b1));
            Vs16[chl * 66 + r8]       = __half_as_ushort(__float2half_rn(acc[ns][2] + b0));
            Vs16[(chl + 1) * 66 + r8] = __half_as_ushort(__float2half_rn(acc[ns][3] + b1));
        }
        __syncthreads();
        // cooperative write in packed layout: 64 ch x 32 key-pairs = 2048 u32
        int tile0 = (pb + m0) >> 5;
#pragma unroll
        for (int r = 0; r < 8; r++) {
            int idx = tid + r * 256;
            int chl = idx >> 5, kpl = idx & 31;        // kpl: pix-pair 0..31
            u32 v = (u32)Vs16[chl * 66 + 2 * kpl] | ((u32)Vs16[chl * 66 + 2 * kpl + 1] << 16);
            int tileIdx = tile0 + (kpl >> 4);
            g_V16[(size_t)tileIdx * 4096 + (n0 + chl) * 16 + (kpl & 15)] = v;
        }
    } else {
#pragma unroll
        for (int ns = 0; ns < 4; ns++) {
            int co = n0 + ntq * 32 + ns * 8 + 2 * t;
            size_t mg  = (size_t)(pb + m0 + mt * 16 + g);
            size_t mg8 = mg + 8;
            int cp = co - 256;
            g_PQK[mg  * 192 + cp]     = acc[ns][0];
            g_PQK[mg  * 192 + cp + 1] = acc[ns][1];
            g_PQK[mg8 * 192 + cp]     = acc[ns][2];
            g_PQK[mg8 * 192 + cp + 1] = acc[ns][3];
        }
    }
}

// ------------- combine conv taps + BN + ReLU, split Q/K into fp16 hi/lo pairs
__global__ void combine_qk() {
    int inst = blockIdx.y;
    int region = inst >> 3, b = inst & 7;
    int N = c_N[region];
    int idx = blockIdx.x * 256 + threadIdx.x;
    int n = idx >> 4;
    if (n >= N) return;
    int cp = idx & 15, c0 = 2 * cp;
    int Wr = c_Wr[region], Hr = c_Hr[region];
    int pb = c_base[region] + b * N;
    int h = n / Wr, w = n - h * Wr;
    size_t rowp = (size_t)(pb + n) * 192;

    float2 q = *(float2*)&g_PQK[rowp + 32 + c0];
    if (w > 0)      { float2 a = *(float2*)&g_PQK[rowp - 192 + c0]; q.x += a.x; q.y += a.y; }
    if (w < Wr - 1) { float2 a = *(float2*)&g_PQK[rowp + 192 + 64 + c0]; q.x += a.x; q.y += a.y; }
    q.x = fmaxf(fmaf(q.x, g_qsc[c0], g_qof[c0]), 0.f);
    q.y = fmaxf(fmaf(q.y, g_qsc[c0 + 1], g_qof[c0 + 1]), 0.f);
    g_Q16h[(size_t)(pb + n) * 16 + cp] = pack2(q.x, q.y);
    g_Q16l[(size_t)(pb + n) * 16 + cp] = pack2(q.x - f16r(q.x), q.y - f16r(q.y));

    float2 k = *(float2*)&g_PQK[rowp + 96 + 32 + c0];
    if (h > 0)      { float2 a = *(float2*)&g_PQK[rowp - (size_t)Wr * 192 + 96 + c0]; k.x += a.x; k.y += a.y; }
    if (h < Hr - 1) { float2 a = *(float2*)&g_PQK[rowp + (size_t)Wr * 192 + 96 + 64 + c0]; k.x += a.x; k.y += a.y; }
    k.x = fmaxf(fmaf(k.x, g_ksc[c0], g_kof[c0]), 0.f);
    k.y = fmaxf(fmaf(k.y, g_ksc[c0 + 1], g_kof[c0 + 1]), 0.f);
    g_K16h[(size_t)(pb + n) * 16 + cp] = pack2(k.x, k.y);
    g_K16l[(size_t)(pb + n) * 16 + cp] = pack2(k.x - f16r(k.x), k.y - f16r(k.y));
}

// ------------------- fp16 flash attention, 64 q-rows x 64-key tiles (R9 proven)
// 256 threads, 2 CTA/SM. mode 0: out = x + delta (shift partition). mode 1: RMW.
// smem offsets in u32 units:
#define OKH 0          // 2 stages x 64x20
#define OKL 2560
#define OVS 5120       // 2 stages x 256x36
#define OP16 23552     // 64 x 36
#define OWM 25856      // wmax [2][64]
#define OWS 25984      // wsum [2][64]
#define OSTAT 26112    // rmax/rsum/rscale/pas 4x64
#define ASMEM (26368 * 4)

__global__ __launch_bounds__(256, 2) void attn(const float* __restrict__ gamma,
                                               const float* __restrict__ xin,
                                               float* __restrict__ out,
                                               int inst0, int mode) {
    extern __shared__ u32 sm32[];
    u32* Ps16 = sm32 + OP16;
    float* wmax = (float*)(sm32 + OWM);
    float* wsum = (float*)(sm32 + OWS);
    float* rmax = (float*)(sm32 + OSTAT);
    float* rsum = rmax + 64;
    float* rscale = rsum + 64;
    int* pas = (int*)(rscale + 64);
    float* stage = (float*)(sm32 + OVS);   // epilogue union over V buffers

    u32 smb = (u32)__cvta_generic_to_shared(sm32);

    int inst = inst0 + blockIdx.y;
    int region = inst >> 3, b = inst & 7;
    int N = c_N[region];
    int n0 = blockIdx.x * 64;
    if (n0 >= N) return;
    int pb = c_base[region] + b * N;

    int tid = threadIdx.x;
    int lane = tid & 31, w = tid >> 5;
    int g = lane >> 2, t = lane & 3;
    if (tid < 64) {
        rmax[tid] = -1e30f; rsum[tid] = 0.f;
        pas[tid] = g_pix[pb + n0 + tid];
    }

    int mt = w & 3, ntk = w >> 2;             // S mapping: rows mt*16, keys ntk*32
    int wm = w & 3, wslab = (w >> 2) * 128;   // PV mapping
    int rowg = mt * 16 + g;

    // Q fragments hi/lo in registers (fixed per CTA)
    u32 aqh[2][4], aql[2][4];
    {
        size_t r0 = (size_t)(pb + n0 + rowg) * 16;
        size_t r8 = r0 + 128;   // +8 rows * 16
#pragma unroll
        for (int kt = 0; kt < 2; kt++) {
            int c = kt * 8 + t;
            aqh[kt][0] = g_Q16h[r0 + c];     aqh[kt][1] = g_Q16h[r8 + c];
            aqh[kt][2] = g_Q16h[r0 + c + 4]; aqh[kt][3] = g_Q16h[r8 + c + 4];
            aql[kt][0] = g_Q16l[r0 + c];     aql[kt][1] = g_Q16l[r8 + c];
            aql[kt][2] = g_Q16l[r0 + c + 4]; aql[kt][3] = g_Q16l[r8 + c + 4];
        }
    }

    // prefetch addressing
    int kidx = tid & 127;
    const u32* ksrc = (tid < 128) ? g_K16h : g_K16l;
    u32 kdst = (tid < 128) ? (u32)OKH : (u32)OKL;

    float acc[16][4];
#pragma unroll
    for (int nt = 0; nt < 16; nt++)
#pragma unroll
        for (int r = 0; r < 4; r++) acc[nt][r] = 0.f;

    int nmt = N >> 6;
    // prologue: prefetch tile 0 into stage 0
    {
        int mb = pb;
#pragma unroll
        for (int r = 0; r < 2; r++) {
            int chunk = kidx + r * 128;
            int krow = chunk >> 2, kc4 = chunk & 3;
            cpa16(smb + (kdst + krow * 20 + kc4 * 4) * 4, &ksrc[(size_t)(mb + krow) * 16 + kc4 * 4]);
        }
        size_t vbase = (size_t)(mb >> 5) * 4096;
#pragma unroll
        for (int r = 0; r < 8; r++) {
            int idx = tid + r * 256;
            int ch = idx >> 3, sub = idx & 7;
            int half = sub >> 2, c4 = sub & 3;
            cpa16(smb + (OVS + ch * 36 + half * 16 + c4 * 4) * 4,
                  &g_V16[vbase + (size_t)half * 4096 + ch * 16 + c4 * 4]);
        }
        CPA_COMMIT;
    }

    for (int it = 0; it < nmt; it++) {
        int s = it & 1;
        __syncthreads();                       // readers of stage s^1 done
        if (it + 1 < nmt) {
            int mb = pb + (it + 1) * 64;
            int s2 = (it + 1) & 1;
#pragma unroll
            for (int r = 0; r < 2; r++) {
                int chunk = kidx + r * 128;
                int krow = chunk >> 2, kc4 = chunk & 3;
                cpa16(smb + (kdst + s2 * 1280 + krow * 20 + kc4 * 4) * 4,
                      &ksrc[(size_t)(mb + krow) * 16 + kc4 * 4]);
            }
            size_t vbase = (size_t)(mb >> 5) * 4096;
#pragma unroll
            for (int r = 0; r < 8; r++) {
                int idx = tid + r * 256;
                int ch = idx >> 3, sub = idx & 7;
                int half = sub >> 2, c4 = sub & 3;
                cpa16(smb + (OVS + s2 * 9216 + ch * 36 + half * 16 + c4 * 4) * 4,
                      &g_V16[vbase + (size_t)half * 4096 + ch * 16 + c4 * 4]);
            }
            CPA_COMMIT;
            CPA_WAIT1;
        } else {
            CPA_WAIT0;
        }
        __syncthreads();                       // tile data visible
        u32* Kh = sm32 + OKH + s * 1280;
        u32* Kl = sm32 + OKL + s * 1280;
        u32* Vs = sm32 + OVS + s * 9216;

        // ---- S: split-fp16, warp does 16 rows x 32 keys (registers)
        float sacc[4][4];
#pragma unroll
        for (int i = 0; i < 4; i++)
#pragma unroll
            for (int j = 0; j < 4; j++) sacc[i][j] = 0.f;
#pragma unroll
        for (int kt = 0; kt < 2; kt++) {
            u32 ah0 = aqh[kt][0], ah1 = aqh[kt][1], ah2 = aqh[kt][2], ah3 = aqh[kt][3];
            u32 al0 = aql[kt][0], al1 = aql[kt][1], al2 = aql[kt][2], al3 = aql[kt][3];
#pragma unroll
            for (int sub = 0; sub < 4; sub++) {
                int kr = (ntk * 32 + sub * 8 + g) * 20 + kt * 8 + t;
                u32 bh0 = Kh[kr], bh1 = Kh[kr + 4];
                u32 bl0 = Kl[kr], bl1 = Kl[kr + 4];
                MMA_F16(sacc[sub], ah0, ah1, ah2, ah3, bh0, bh1);
                MMA_F16(sacc[sub], al0, al1, al2, al3, bh0, bh1);
                MMA_F16(sacc[sub], ah0, ah1, ah2, ah3, bl0, bl1);
            }
        }
        // ---- softmax phase A: warp-local row max over 32 keys
        float m0 = fmaxf(fmaxf(sacc[0][0], sacc[0][1]), fmaxf(sacc[1][0], sacc[1][1]));
        m0 = fmaxf(m0, fmaxf(fmaxf(sacc[2][0], sacc[2][1]), fmaxf(sacc[3][0], sacc[3][1])));
        float m1 = fmaxf(fmaxf(sacc[0][2], sacc[0][3]), fmaxf(sacc[1][2], sacc[1][3]));
        m1 = fmaxf(m1, fmaxf(fmaxf(sacc[2][2], sacc[2][3]), fmaxf(sacc[3][2], sacc[3][3])));
        m0 = fmaxf(m0, __shfl_xor_sync(0xffffffffu, m0, 1));
        m0 = fmaxf(m0, __shfl_xor_sync(0xffffffffu, m0, 2));
        m1 = fmaxf(m1, __shfl_xor_sync(0xffffffffu, m1, 1));
        m1 = fmaxf(m1, __shfl_xor_sync(0xffffffffu, m1, 2));
        float rm0 = rmax[rowg], rm1 = rmax[rowg + 8];
        if (t == 0) {
            wmax[ntk * 64 + rowg]     = m0;
            wmax[ntk * 64 + rowg + 8] = m1;
        }
        __syncthreads();                       // wmax visible
        // ---- softmax phase B: exp in registers, pack to Ps16
        float nm0 = fmaxf(rm0, fmaxf(wmax[rowg], wmax[64 + rowg]));
        float nm1 = fmaxf(rm1, fmaxf(wmax[rowg + 8], wmax[64 + rowg + 8]));
        float s0 = 0.f, s1 = 0.f;
#pragma unroll
        for (int sub = 0; sub < 4; sub++) {
            float p00 = __expf(sacc[sub][0] - nm0);
            float p01 = __expf(sacc[sub][1] - nm0);
            float p10 = __expf(sacc[sub][2] - nm1);
            float p11 = __expf(sacc[sub][3] - nm1);
            s0 += p00 + p01; s1 += p10 + p11;
            int kp = ntk * 16 + sub * 4 + t;
            Ps16[rowg * 36 + kp]       = pack2(p00, p01);
            Ps16[(rowg + 8) * 36 + kp] = pack2(p10, p11);
        }
        s0 += __shfl_xor_sync(0xffffffffu, s0, 1);
        s0 += __shfl_xor_sync(0xffffffffu, s0, 2);
        s1 += __shfl_xor_sync(0xffffffffu, s1, 1);
        s1 += __shfl_xor_sync(0xffffffffu, s1, 2);
        if (t == 0) {
            wsum[ntk * 64 + rowg]     = s0;
            wsum[ntk * 64 + rowg + 8] = s1;
            if (ntk == 0) {
                rscale[rowg]     = __expf(rm0 - nm0);
                rscale[rowg + 8] = __expf(rm1 - nm1);
                rmax[rowg] = nm0; rmax[rowg + 8] = nm1;
            }
        }
        __syncthreads();                       // Ps16 + rscale + wsum visible
        // ---- PV: rescale + fp16 MMA (warp: 16 rows x 128 ch, 64 keys)
        {
            float sc0 = rscale[wm * 16 + g];
            float sc1 = rscale[wm * 16 + g + 8];
#pragma unroll
            for (int nt = 0; nt < 16; nt++) {
                acc[nt][0] *= sc0; acc[nt][1] *= sc0;
                acc[nt][2] *= sc1; acc[nt][3] *= sc1;
            }
#pragma unroll
            for (int kt = 0; kt < 4; kt++) {
                int pr = (wm * 16 + g) * 36 + kt * 8 + t;
                u32 pa0 = Ps16[pr], pa1 = Ps16[pr + 288], pa2 = Ps16[pr + 4], pa3 = Ps16[pr + 292];
#pragma unroll
                for (int nt = 0; nt < 16; nt++) {
                    int vr = (wslab + nt * 8 + g) * 36 + kt * 8 + t;
                    MMA_F16(acc[nt], pa0, pa1, pa2, pa3, Vs[vr], Vs[vr + 4]);
                }
            }
        }
        // running-sum update (rsum read only at epilogue)
        if (w < 4 && lane < 16) {
            int row = w * 16 + lane;
            rsum[row] = rsum[row] * rscale[row] + wsum[row] + wsum[64 + row];
        }
    }
    // epilogue: two passes of 32 rows staged, then coalesced write/RMW
    float gm = 0.5f * gamma[0];
#pragma unroll
    for (int pass = 0; pass < 2; pass++) {
        __syncthreads();
        if ((wm >> 1) == pass) {
            float f0 = gm / rsum[wm * 16 + g];
            float f1 = gm / rsum[wm * 16 + g + 8];
            int row0 = (wm * 16 + g) - pass * 32;
            int r0 = row0 * 264 + wslab + 2 * t;
            int r8 = (row0 + 8) * 264 + wslab + 2 * t;
#pragma unroll
            for (int nt = 0; nt < 16; nt++) {
                stage[r0 + nt * 8]     = acc[nt][0] * f0;
                stage[r0 + nt * 8 + 1] = acc[nt][1] * f0;
                stage[r8 + nt * 8]     = acc[nt][2] * f1;
                stage[r8 + nt * 8 + 1] = acc[nt][3] * f1;
            }
        }
        __syncthreads();
        int tn = tid & 7, tc = tid >> 3;
#pragma unroll
        for (int i = 0; i < 4; i++) {
            int row = tn + 8 * i;
            int pa = pas[pass * 32 + row];
#pragma unroll
            for (int j = 0; j < 8; j++) {
                int c = tc * 8 + j;
                float vv = stage[row * 264 + c];
                if (mode) out[pa + c * HW] += vv;
                else      out[pa + c * HW] = xin[pa + c * HW] + vv;
            }
        }
    }
}

// ---------------------------------------------------------------- launcher
extern "C" void kernel_launch(void* const* d_in, const int* in_sizes, int n_in,
                              void* d_out, int out_size) {
    const float* x   = (const float*)d_in[0];
    const float* Wq  = (const float*)d_in[1];
    const float* bq  = (const float*)d_in[2];
    const float* q_s = (const float*)d_in[3];
    const float* q_o = (const float*)d_in[4];
    const float* q_m = (const float*)d_in[5];
    const float* q_v = (const float*)d_in[6];
    const float* Wk  = (const float*)d_in[7];
    const float* bk  = (const float*)d_in[8];
    const float* k_s = (const float*)d_in[9];
    const float* k_o = (const float*)d_in[10];
    const float* k_m = (const float*)d_in[11];
    const float* k_v = (const float*)d_in[12];
    const float* Wv  = (const float*)d_in[13];
    const float* bv  = (const float*)d_in[14];
    const float* gam = (const float*)d_in[15];
    float* out = (float*)d_out;

    cudaFuncSetAttribute(attn, cudaFuncAttributeMaxDynamicSharedMemorySize, ASMEM);

    prep_wall<<<224, 256>>>(Wq, Wk, Wv);
    prep_bn<<<1, 32>>>(bq, q_s, q_o, q_m, q_v, bk, k_s, k_o, k_m, k_v);
    prep_pix<<<dim3(6, 232), 256>>>();
    x_pack<<<TOTPIX / 32, 256>>>(x);
    qkv_gemm<<<dim3(7, 24, 232), 256, QSMEM>>>(bv);
    combine_qk<<<dim3(96, 232), 256>>>();
    // shift regions (12..28) partition the image: write mode (out = x + delta)
    attn<<<dim3(24, 136), 256, ASMEM>>>(gam, x, out, 96, 0);
    // win regions (0..11): disjoint pixels within launch -> RMW
    attn<<<dim3(16, 96), 256, ASMEM>>>(gam, x, out, 0, 1);
}

// round 15
// speedup vs baseline: 1.1172x; 1.0059x over previous
#include <cuda_runtime.h>
#include <cuda_fp16.h>
#include <math.h>
#include <stdint.h>

// Problem constants (B=8, C=256, H=W=128, win_n=4, shift=16)
#define HW   16384
#define IMG  128
#define NREG 29
#define TOTPIX 229376
#define COUT 448        // 256 V + 96 Pq(3 taps x 32) + 96 Pk

typedef uint32_t u32;
typedef unsigned short u16;

__device__ __forceinline__ float f16r(float v) {
    return __half2float(__float2half_rn(v));
}
__device__ __forceinline__ u32 pack2(float e0, float e1) {   // e0 -> lo half
    __half2 h = __floats2half2_rn(e0, e1);
    return *reinterpret_cast<u32*>(&h);
}

// m16n8k16 fp16 MMA, fp32 accumulate
#define MMA_F16(d, a0, a1, a2, a3, b0, b1)                                           \
    asm volatile("mma.sync.aligned.m16n8k16.row.col.f32.f16.f16.f32 "                \
                 "{%0,%1,%2,%3},{%4,%5,%6,%7},{%8,%9},{%0,%1,%2,%3};"                \
                 : "+f"(d[0]), "+f"(d[1]), "+f"(d[2]), "+f"(d[3])                    \
                 : "r"(a0), "r"(a1), "r"(a2), "r"(a3), "r"(b0), "r"(b1))

__device__ __forceinline__ void cpa16(u32 dst, const u32* src) {
    asm volatile("cp.async.cg.shared.global [%0], [%1], 16;" :: "r"(dst), "l"(src));
}
#define CPA_COMMIT asm volatile("cp.async.commit_group;")
#define CPA_WAIT0  asm volatile("cp.async.wait_all;")

// Region tables: 12 win (rows 1..3 x cols 0..3), 9 shift-inner, 8 borders
__constant__ int c_h0[NREG] = {32,32,32,32, 64,64,64,64, 96,96,96,96,
                               16,16,16, 48,48,48, 80,80,80,
                               0,0,0, 16,16, 112,112,112};
__constant__ int c_w0[NREG] = {0,32,64,96, 0,32,64,96, 0,32,64,96,
                               16,48,80, 16,48,80, 16,48,80,
                               0,16,112, 0,112, 0,16,112};
__constant__ int c_Hr[NREG] = {32,32,32,32,32,32,32,32,32,32,32,32,
                               32,32,32,32,32,32,32,32,32,
                               16,16,16, 96,96, 16,16,16};
__constant__ int c_Wr[NREG] = {32,32,32,32,32,32,32,32,32,32,32,32,
                               32,32,32,32,32,32,32,32,32,
                               16,96,16, 16,16, 16,96,16};
__constant__ int c_N[NREG]  = {1024,1024,1024,1024,1024,1024,1024,1024,1024,1024,1024,1024,
                               1024,1024,1024,1024,1024,1024,1024,1024,1024,
                               256,1536,256, 1536,1536, 256,1536,256};
__constant__ int c_base[NREG] = {0,8192,16384,24576,32768,40960,49152,57344,65536,73728,81920,90112,
                                 98304,106496,114688,122880,131072,139264,147456,155648,163840,
                                 172032,174080,186368, 188416,200704, 212992,215040,227328};

// Scratch (__device__ globals)
static __device__ u32   g_W16h[COUT * 128];                  // [co][ci-pair] fp16x2 hi
static __device__ u32   g_W16l[COUT * 128];                  // lo residual
static __device__ u32   g_X16h[(size_t)TOTPIX * 128];        // [pix][ci-pair] fp16x2 hi
static __device__ u32   g_X16l[(size_t)TOTPIX * 128];        // lo residual
static __device__ u32   g_V16 [(size_t)TOTPIX * 128];        // [tile32][ch][key-pair]
static __device__ float g_PQK[(size_t)TOTPIX * 192];
static __device__ u32   g_Q16h[(size_t)TOTPIX * 16];         // [pix][d-pair]
static __device__ u32   g_Q16l[(size_t)TOTPIX * 16];
static __device__ u32   g_K16h[(size_t)TOTPIX * 16];
static __device__ u32   g_K16l[(size_t)TOTPIX * 16];
static __device__ int   g_pix[TOTPIX];
static __device__ float g_qsc[32], g_qof[32], g_ksc[32], g_kof[32];

// ---------------------------------------------------------------- prep kernels
__device__ __forceinline__ float wall_val(const float* Wq, const float* Wk,
                                          const float* Wv, int co, int ci) {
    if (co < 256) return Wv[co * 256 + ci];
    if (co < 352) { int t = (co - 256) >> 5, c8 = (co - 256) & 31;
                    return Wq[(c8 * 256 + ci) * 3 + t]; }
    { int t = (co - 352) >> 5, c8 = (co - 352) & 31;
      return Wk[(c8 * 256 + ci) * 3 + t]; }
}

__global__ void prep_wall(const float* __restrict__ Wq, const float* __restrict__ Wk,
                          const float* __restrict__ Wv) {
    int idx = blockIdx.x * 256 + threadIdx.x;
    if (idx >= COUT * 128) return;
    int co = idx >> 7, cp = idx & 127;
    float v0 = wall_val(Wq, Wk, Wv, co, 2 * cp);
    float v1 = wall_val(Wq, Wk, Wv, co, 2 * cp + 1);
    g_W16h[idx] = pack2(v0, v1);
    g_W16l[idx] = pack2(v0 - f16r(v0), v1 - f16r(v1));
}

__global__ void prep_bn(const float* bq, const float* qs, const float* qo, const float* qm, const float* qv,
                        const float* bk, const float* ks, const float* ko, const float* km, const float* kv) {
    int c = threadIdx.x;
    if (c >= 32) return;
    float sc = qs[c] * rsqrtf(qv[c] + 1e-5f);
    g_qsc[c] = sc;
    g_qof[c] = bq[c] * sc + qo[c] - qm[c] * sc;
    sc = ks[c] * rsqrtf(kv[c] + 1e-5f);
    g_ksc[c] = sc;
    g_kof[c] = bk[c] * sc + ko[c] - km[c] * sc;
}

__global__ void prep_pix() {
    int inst = blockIdx.y;
    int region = inst >> 3, b = inst & 7;
    int N = c_N[region];
    int n = blockIdx.x * 256 + threadIdx.x;
    if (n >= N) return;
    int Wr = c_Wr[region];
    int h = n / Wr, w = n - h * Wr;
    g_pix[c_base[region] + b * N + n] = b * (256 * HW) + (c_h0[region] + h) * IMG + c_w0[region] + w;
}

// ---------------- x_pack: one-time transpose-gather of x into fp16 hi/lo
__global__ __launch_bounds__(256) void x_pack(const float* __restrict__ x) {
    __shared__ u16 Xh[256 * 33];
    __shared__ u16 Xl[256 * 33];
    __shared__ int pas[32];
    int tid = threadIdx.x;
    int pixbase = blockIdx.x * 32;
    if (tid < 32) pas[tid] = g_pix[pixbase + tid];
    __syncthreads();
    int m = tid & 31, cw = tid >> 5;
#pragma unroll
    for (int r = 0; r < 32; r++) {
        int ci = cw + r * 8;
        float v = x[pas[m] + ci * HW];
        float h = f16r(v);
        Xh[ci * 33 + m] = __half_as_ushort(__float2half_rn(v));
        Xl[ci * 33 + m] = __half_as_ushort(__float2half_rn(v - h));
    }
    __syncthreads();
#pragma unroll
    for (int r = 0; r < 16; r++) {
        int idx = tid + r * 256;
        int mm = idx >> 7, cp = idx & 127;
        size_t o = (size_t)(pixbase + mm) * 128 + cp;
        g_X16h[o] = (u32)Xh[(2 * cp) * 33 + mm] | ((u32)Xh[(2 * cp + 1) * 33 + mm] << 16);
        g_X16l[o] = (u32)Xl[(2 * cp) * 33 + mm] | ((u32)Xl[(2 * cp + 1) * 33 + mm] << 16);
    }
}

// ---------------- QKV GEMM: [pix,256]@[256,448], cp.async pipeline, 1 sync/chunk
// V-column tiles (n0<256): plain fp16, packed-layout output. QK tiles: split x3.
#define QAH 0
#define QAL 2560
#define QBH 5120
#define QBL 7680
#define QSMEM (10240 * 4)

__global__ __launch_bounds__(256) void qkv_gemm(const float* __restrict__ bv) {
    extern __shared__ u32 qsm[];
    u16* Vs16 = (u16*)qsm;         // epilogue alias (after k-loop + sync)
    u32 smb = (u32)__cvta_generic_to_shared(qsm);

    int inst = blockIdx.z;
    int region = inst >> 3, b = inst & 7;
    int N = c_N[region];
    int m0 = blockIdx.y * 64;
    if (m0 >= N) return;
    int pb = c_base[region] + b * N;
    int n0 = blockIdx.x * 64;
    bool vt = (n0 < 256);          // pure-V tile: plain fp16

    int tid = threadIdx.x;
    int lane = tid & 31, w = tid >> 5;
    int g = lane >> 2, t = lane & 3;
    int mt = w & 3, ntq = w >> 2;

    // prefetch addressing: row = tid>>2 (0..63), c4 = tid&3
    int prow = tid >> 2, pc4 = tid & 3;
    u32 sdst = (prow * 20 + pc4 * 4) * 4;   // byte offset within a stage
    size_t asrc0 = (size_t)(pb + m0 + prow) * 128 + pc4 * 4;
    size_t bsrc0 = (size_t)(n0 + prow) * 128 + pc4 * 4;

    float acc[4][4];
#pragma unroll
    for (int i = 0; i < 4; i++)
#pragma unroll
        for (int j = 0; j < 4; j++) acc[i][j] = 0.f;

    // prologue: prefetch chunk 0 into stage 0
    {
        cpa16(smb + QAH * 4 + sdst, &g_X16h[asrc0]);
        cpa16(smb + QBH * 4 + sdst, &g_W16h[bsrc0]);
        if (!vt) {
            cpa16(smb + QAL * 4 + sdst, &g_X16l[asrc0]);
            cpa16(smb + QBL * 4 + sdst, &g_W16l[bsrc0]);
        }
        CPA_COMMIT;
    }

    for (int it = 0; it < 8; it++) {         // 8 chunks of k=32
        int s = it & 1;
        CPA_WAIT0;                           // stage s data arrived (this thread)
        __syncthreads();                     // stage s visible to all; stage s^1 free
        if (it + 1 < 8) {                    // issue next chunk: overlaps full MMA
            int s2 = (it + 1) & 1;
            size_t ko = (size_t)(it + 1) * 16;   // k-pairs
            cpa16(smb + (QAH + s2 * 1280) * 4 + sdst, &g_X16h[asrc0 + ko]);
            cpa16(smb + (QBH + s2 * 1280) * 4 + sdst, &g_W16h[bsrc0 + ko]);
            if (!vt) {
                cpa16(smb + (QAL + s2 * 1280) * 4 + sdst, &g_X16l[asrc0 + ko]);
                cpa16(smb + (QBL + s2 * 1280) * 4 + sdst, &g_W16l[bsrc0 + ko]);
            }
            CPA_COMMIT;
        }
        u32* Ah = qsm + QAH + s * 1280;
        u32* Al = qsm + QAL + s * 1280;
        u32* Bh = qsm + QBH + s * 1280;
        u32* Bl = qsm + QBL + s * 1280;
#pragma unroll
        for (int kt = 0; kt < 2; kt++) {
            int ar = (mt * 16 + g) * 20 + kt * 8 + t;
            u32 ah0 = Ah[ar], ah1 = Ah[ar + 160], ah2 = Ah[ar + 4], ah3 = Ah[ar + 164];
#pragma unroll
            for (int ns = 0; ns < 4; ns++) {
                int nr = (ntq * 32 + ns * 8 + g) * 20 + kt * 8 + t;
                u32 bh0 = Bh[nr], bh1 = Bh[nr + 4];
                MMA_F16(acc[ns], ah0, ah1, ah2, ah3, bh0, bh1);
                if (!vt) {
                    u32 al0 = Al[ar], al1 = Al[ar + 160], al2 = Al[ar + 4], al3 = Al[ar + 164];
                    u32 bl0 = Bl[nr], bl1 = Bl[nr + 4];
                    MMA_F16(acc[ns], al0, al1, al2, al3, bh0, bh1);
                    MMA_F16(acc[ns], ah0, ah1, ah2, ah3, bl0, bl1);
                }
            }
        }
    }
    if (vt) {
        __syncthreads();   // all fragment reads done before aliasing stage smem
        int r0 = mt * 16 + g, r8 = r0 + 8;
#pragma unroll
        for (int ns = 0; ns < 4; ns++) {
            int co = n0 + ntq * 32 + ns * 8 + 2 * t;
            int chl = co - n0;
            float b0 = bv[co], b1 = bv[co + 1];
            Vs16[chl * 66 + r0]       = __half_as_ushort(__float2half_rn(acc[ns][0] + b0));
            Vs16[(chl + 1) * 66 + r0] = __half_as_ushort(__float2half_rn(acc[ns][1] + b1));
            Vs16[chl * 66 + r8]       = __half_as_ushort(__float2half_rn(acc[ns][2] + b0));
            Vs16[(chl + 1) * 66 + r8] = __half_as_ushort(__float2half_rn(acc[ns][3] + b1));
        }
        __syncthreads();
        int tile0 = (pb + m0) >> 5;
#pragma unroll
        for (int r = 0; r < 8; r++) {
            int idx = tid + r * 256;
            int chl = idx >> 5, kpl = idx & 31;        // kpl: pix-pair 0..31
            u32 v = (u32)Vs16[chl * 66 + 2 * kpl] | ((u32)Vs16[chl * 66 + 2 * kpl + 1] << 16);
            int tileIdx = tile0 + (kpl >> 4);
            g_V16[(size_t)tileIdx * 4096 + (n0 + chl) * 16 + (kpl & 15)] = v;
        }
    } else {
#pragma unroll
        for (int ns = 0; ns < 4; ns++) {
            int co = n0 + ntq * 32 + ns * 8 + 2 * t;
            size_t mg  = (size_t)(pb + m0 + mt * 16 + g);
            size_t mg8 = mg + 8;
            int cp = co - 256;
            g_PQK[mg  * 192 + cp]     = acc[ns][0];
            g_PQK[mg  * 192 + cp + 1] = acc[ns][1];
            g_PQK[mg8 * 192 + cp]     = acc[ns][2];
            g_PQK[mg8 * 192 + cp + 1] = acc[ns][3];
        }
    }
}

// ------------- combine conv taps + BN + ReLU, split Q/K into fp16 hi/lo pairs
__global__ void combine_qk() {
    int inst = blockIdx.y;
    int region = inst >> 3, b = inst & 7;
    int N = c_N[region];
    int idx = blockIdx.x * 256 + threadIdx.x;
    int n = idx >> 4;
    if (n >= N) return;
    int cp = idx & 15, c0 = 2 * cp;
    int Wr = c_Wr[region], Hr = c_Hr[region];
    int pb = c_base[region] + b * N;
    int h = n / Wr, w = n - h * Wr;
    size_t rowp = (size_t)(pb + n) * 192;

    float2 q = *(float2*)&g_PQK[rowp + 32 + c0];
    if (w > 0)      { float2 a = *(float2*)&g_PQK[rowp - 192 + c0]; q.x += a.x; q.y += a.y; }
    if (w < Wr - 1) { float2 a = *(float2*)&g_PQK[rowp + 192 + 64 + c0]; q.x += a.x; q.y += a.y; }
    q.x = fmaxf(fmaf(q.x, g_qsc[c0], g_qof[c0]), 0.f);
    q.y = fmaxf(fmaf(q.y, g_qsc[c0 + 1], g_qof[c0 + 1]), 0.f);
    g_Q16h[(size_t)(pb + n) * 16 + cp] = pack2(q.x, q.y);
    g_Q16l[(size_t)(pb + n) * 16 + cp] = pack2(q.x - f16r(q.x), q.y - f16r(q.y));

    float2 k = *(float2*)&g_PQK[rowp + 96 + 32 + c0];
    if (h > 0)      { float2 a = *(float2*)&g_PQK[rowp - (size_t)Wr * 192 + 96 + c0]; k.x += a.x; k.y += a.y; }
    if (h < Hr - 1) { float2 a = *(float2*)&g_PQK[rowp + (size_t)Wr * 192 + 96 + 64 + c0]; k.x += a.x; k.y += a.y; }
    k.x = fmaxf(fmaf(k.x, g_ksc[c0], g_kof[c0]), 0.f);
    k.y = fmaxf(fmaf(k.y, g_ksc[c0 + 1], g_kof[c0 + 1]), 0.f);
    g_K16h[(size_t)(pb + n) * 16 + cp] = pack2(k.x, k.y);
    g_K16l[(size_t)(pb + n) * 16 + cp] = pack2(k.x - f16r(k.x), k.y - f16r(k.y));
}

// ------------------- fp16 flash attention, 64 q-rows x 64-key tiles
// 256 threads, 2 CTA/SM, 3 syncs/tile. mode 0: out = x + delta. mode 1: RMW.
#define OKH 0          // 2 stages x 64x20
#define OKL 2560
#define OVS 5120       // 2 stages x 256x36
#define OP16 23552     // 64 x 36
#define OWM 25856      // wmax [2][64]
#define OWS 25984      // wsum [2][64]
#define OSTAT 26112    // rmax/rsum/rscale/pas 4x64
#define ASMEM (26368 * 4)

__global__ __launch_bounds__(256, 2) void attn(const float* __restrict__ gamma,
                                               const float* __restrict__ xin,
                                               float* __restrict__ out,
                                               int inst0, int mode) {
    extern __shared__ u32 sm32[];
    u32* Ps16 = sm32 + OP16;
    float* wmax = (float*)(sm32 + OWM);
    float* wsum = (float*)(sm32 + OWS);
    float* rmax = (float*)(sm32 + OSTAT);
    float* rsum = rmax + 64;
    float* rscale = rsum + 64;
    int* pas = (int*)(rscale + 64);
    float* stage = (float*)(sm32 + OVS);   // epilogue union over V buffers

    u32 smb = (u32)__cvta_generic_to_shared(sm32);

    int inst = inst0 + blockIdx.y;
    int region = inst >> 3, b = inst & 7;
    int N = c_N[region];
    int n0 = blockIdx.x * 64;
    if (n0 >= N) return;
    int pb = c_base[region] + b * N;

    int tid = threadIdx.x;
    int lane = tid & 31, w = tid >> 5;
    int g = lane >> 2, t = lane & 3;
    if (tid < 64) {
        rmax[tid] = -1e30f; rsum[tid] = 0.f;
        pas[tid] = g_pix[pb + n0 + tid];
    }

    int mt = w & 3, ntk = w >> 2;             // S mapping: rows mt*16, keys ntk*32
    int wm = w & 3, wslab = (w >> 2) * 128;   // PV mapping
    int rowg = mt * 16 + g;

    // Q fragments hi/lo in registers (fixed per CTA)
    u32 aqh[2][4], aql[2][4];
    {
        size_t r0 = (size_t)(pb + n0 + rowg) * 16;
        size_t r8 = r0 + 128;   // +8 rows * 16
#pragma unroll
        for (int kt = 0; kt < 2; kt++) {
            int c = kt * 8 + t;
            aqh[kt][0] = g_Q16h[r0 + c];     aqh[kt][1] = g_Q16h[r8 + c];
            aqh[kt][2] = g_Q16h[r0 + c + 4]; aqh[kt][3] = g_Q16h[r8 + c + 4];
            aql[kt][0] = g_Q16l[r0 + c];     aql[kt][1] = g_Q16l[r8 + c];
            aql[kt][2] = g_Q16l[r0 + c + 4]; aql[kt][3] = g_Q16l[r8 + c + 4];
        }
    }

    // prefetch addressing
    int kidx = tid & 127;
    const u32* ksrc = (tid < 128) ? g_K16h : g_K16l;
    u32 kdst = (tid < 128) ? (u32)OKH : (u32)OKL;

    float acc[16][4];
#pragma unroll
    for (int nt = 0; nt < 16; nt++)
#pragma unroll
        for (int r = 0; r < 4; r++) acc[nt][r] = 0.f;

    int nmt = N >> 6;
    // prologue: prefetch tile 0 into stage 0
    {
        int mb = pb;
#pragma unroll
        for (int r = 0; r < 2; r++) {
            int chunk = kidx + r * 128;
            int krow = chunk >> 2, kc4 = chunk & 3;
            cpa16(smb + (kdst + krow * 20 + kc4 * 4) * 4, &ksrc[(size_t)(mb + krow) * 16 + kc4 * 4]);
        }
        size_t vbase = (size_t)(mb >> 5) * 4096;
#pragma unroll
        for (int r = 0; r < 8; r++) {
            int idx = tid + r * 256;
            int ch = idx >> 3, sub = idx & 7;
            int half = sub >> 2, c4 = sub & 3;
            cpa16(smb + (OVS + ch * 36 + half * 16 + c4 * 4) * 4,
                  &g_V16[vbase + (size_t)half * 4096 + ch * 16 + c4 * 4]);
        }
        CPA_COMMIT;
    }

    for (int it = 0; it < nmt; it++) {
        int s = it & 1;
        CPA_WAIT0;                             // stage s data arrived (this thread)
        __syncthreads();                       // B: stage s visible; s^1 + Ps16 free
        if (it + 1 < nmt) {                    // issue next tile: overlaps S+exp+PV
            int mb = pb + (it + 1) * 64;
            int s2 = (it + 1) & 1;
#pragma unroll
            for (int r = 0; r < 2; r++) {
                int chunk = kidx + r * 128;
                int krow = chunk >> 2, kc4 = chunk & 3;
                cpa16(smb + (kdst + s2 * 1280 + krow * 20 + kc4 * 4) * 4,
                      &ksrc[(size_t)(mb + krow) * 16 + kc4 * 4]);
            }
            size_t vbase = (size_t)(mb >> 5) * 4096;
#pragma unroll
            for (int r = 0; r < 8; r++) {
                int idx = tid + r * 256;
                int ch = idx >> 3, sub = idx & 7;
                int half = sub >> 2, c4 = sub & 3;
                cpa16(smb + (OVS + s2 * 9216 + ch * 36 + half * 16 + c4 * 4) * 4,
                      &g_V16[vbase + (size_t)half * 4096 + ch * 16 + c4 * 4]);
            }
            CPA_COMMIT;
        }
        u32* Kh = sm32 + OKH + s * 1280;
        u32* Kl = sm32 + OKL + s * 1280;
        u32* Vs = sm32 + OVS + s * 9216;

        // ---- S: split-fp16, warp does 16 rows x 32 keys (registers)
        float sacc[4][4];
#pragma unroll
        for (int i = 0; i < 4; i++)
#pragma unroll
            for (int j = 0; j < 4; j++) sacc[i][j] = 0.f;
#pragma unroll
        for (int kt = 0; kt < 2; kt++) {
            u32 ah0 = aqh[kt][0], ah1 = aqh[kt][1], ah2 = aqh[kt][2], ah3 = aqh[kt][3];
            u32 al0 = aql[kt][0], al1 = aql[kt][1], al2 = aql[kt][2], al3 = aql[kt][3];
#pragma unroll
            for (int sub = 0; sub < 4; sub++) {
                int kr = (ntk * 32 + sub * 8 + g) * 20 + kt * 8 + t;
                u32 bh0 = Kh[kr], bh1 = Kh[kr + 4];
                u32 bl0 = Kl[kr], bl1 = Kl[kr + 4];
                MMA_F16(sacc[sub], ah0, ah1, ah2, ah3, bh0, bh1);
                MMA_F16(sacc[sub], al0, al1, al2, al3, bh0, bh1);
                MMA_F16(sacc[sub], ah0, ah1, ah2, ah3, bl0, bl1);
            }
        }
        // ---- softmax phase A: warp-local row max over 32 keys
        float m0 = fmaxf(fmaxf(sacc[0][0], sacc[0][1]), fmaxf(sacc[1][0], sacc[1][1]));
        m0 = fmaxf(m0, fmaxf(fmaxf(sacc[2][0], sacc[2][1]), fmaxf(sacc[3][0], sacc[3][1])));
        float m1 = fmaxf(fmaxf(sacc[0][2], sacc[0][3]), fmaxf(sacc[1][2], sacc[1][3]));
        m1 = fmaxf(m1, fmaxf(fmaxf(sacc[2][2], sacc[2][3]), fmaxf(sacc[3][2], sacc[3][3])));
        m0 = fmaxf(m0, __shfl_xor_sync(0xffffffffu, m0, 1));
        m0 = fmaxf(m0, __shfl_xor_sync(0xffffffffu, m0, 2));
        m1 = fmaxf(m1, __shfl_xor_sync(0xffffffffu, m1, 1));
        m1 = fmaxf(m1, __shfl_xor_sync(0xffffffffu, m1, 2));
        float rm0 = rmax[rowg], rm1 = rmax[rowg + 8];
        if (t == 0) {
            wmax[ntk * 64 + rowg]     = m0;
            wmax[ntk * 64 + rowg + 8] = m1;
        }
        __syncthreads();                       // C: wmax visible
        // ---- softmax phase B: exp in registers, pack to Ps16
        float nm0 = fmaxf(rm0, fmaxf(wmax[rowg], wmax[64 + rowg]));
        float nm1 = fmaxf(rm1, fmaxf(wmax[rowg + 8], wmax[64 + rowg + 8]));
        float s0 = 0.f, s1 = 0.f;
#pragma unroll
        for (int sub = 0; sub < 4; sub++) {
            float p00 = __expf(sacc[sub][0] - nm0);
            float p01 = __expf(sacc[sub][1] - nm0);
            float p10 = __expf(sacc[sub][2] - nm1);
            float p11 = __expf(sacc[sub][3] - nm1);
            s0 += p00 + p01; s1 += p10 + p11;
            int kp = ntk * 16 + sub * 4 + t;
            Ps16[rowg * 36 + kp]       = pack2(p00, p01);
            Ps16[(rowg + 8) * 36 + kp] = pack2(p10, p11);
        }
        s0 += __shfl_xor_sync(0xffffffffu, s0, 1);
        s0 += __shfl_xor_sync(0xffffffffu, s0, 2);
        s1 += __shfl_xor_sync(0xffffffffu, s1, 1);
        s1 += __shfl_xor_sync(0xffffffffu, s1, 2);
        if (t == 0) {
            wsum[ntk * 64 + rowg]     = s0;
            wsum[ntk * 64 + rowg + 8] = s1;
            if (ntk == 0) {
                rscale[rowg]     = __expf(rm0 - nm0);
                rscale[rowg + 8] = __expf(rm1 - nm1);
                rmax[rowg] = nm0; rmax[rowg + 8] = nm1;
            }
        }
        __syncthreads();                       // D: Ps16 + rscale + wsum visible
        // ---- PV: rescale + fp16 MMA (warp: 16 rows x 128 ch, 64 keys)
        {
            float sc0 = rscale[wm * 16 + g];
            float sc1 = rscale[wm * 16 + g + 8];
#pragma unroll
            for (int nt = 0; nt < 16; nt++) {
                acc[nt][0] *= sc0; acc[nt][1] *= sc0;
                acc[nt][2] *= sc1; acc[nt][3] *= sc1;
            }
#pragma unroll
            for (int kt = 0; kt < 4; kt++) {
                int pr = (wm * 16 + g) * 36 + kt * 8 + t;
                u32 pa0 = Ps16[pr], pa1 = Ps16[pr + 288], pa2 = Ps16[pr + 4], pa3 = Ps16[pr + 292];
#pragma unroll
                for (int nt = 0; nt < 16; nt++) {
                    int vr = (wslab + nt * 8 + g) * 36 + kt * 8 + t;
                    MMA_F16(acc[nt], pa0, pa1, pa2, pa3, Vs[vr], Vs[vr + 4]);
                }
            }
        }
        // running-sum update (rsum read only at epilogue)
        if (w < 4 && lane < 16) {
            int row = w * 16 + lane;
            rsum[row] = rsum[row] * rscale[row] + wsum[row] + wsum[64 + row];
        }
    }
    // epilogue: two passes of 32 rows staged, then coalesced write/RMW
    float gm = 0.5f * gamma[0];
#pragma unroll
    for (int pass = 0; pass < 2; pass++) {
        __syncthreads();
        if ((wm >> 1) == pass) {
            float f0 = gm / rsum[wm * 16 + g];
            float f1 = gm / rsum[wm * 16 + g + 8];
            int row0 = (wm * 16 + g) - pass * 32;
            int r0 = row0 * 264 + wslab + 2 * t;
            int r8 = (row0 + 8) * 264 + wslab + 2 * t;
#pragma unroll
            for (int nt = 0; nt < 16; nt++) {
                stage[r0 + nt * 8]     = acc[nt][0] * f0;
                stage[r0 + nt * 8 + 1] = acc[nt][1] * f0;
                stage[r8 + nt * 8]     = acc[nt][2] * f1;
                stage[r8 + nt * 8 + 1] = acc[nt][3] * f1;
            }
        }
        __syncthreads();
        int tn = tid & 7, tc = tid >> 3;
#pragma unroll
        for (int i = 0; i < 4; i++) {
            int row = tn + 8 * i;
            int pa = pas[pass * 32 + row];
#pragma unroll
            for (int j = 0; j < 8; j++) {
                int c = tc * 8 + j;
                float vv = stage[row * 264 + c];
                if (mode) out[pa + c * HW] += vv;
                else      out[pa + c * HW] = xin[pa + c * HW] + vv;
            }
        }
    }
}

// ---------------------------------------------------------------- launcher
extern "C" void kernel_launch(void* const* d_in, const int* in_sizes, int n_in,
                              void* d_out, int out_size) {
    const float* x   = (const float*)d_in[0];
    const float* Wq  = (const float*)d_in[1];
    const float* bq  = (const float*)d_in[2];
    const float* q_s = (const float*)d_in[3];
    const float* q_o = (const float*)d_in[4];
    const float* q_m = (const float*)d_in[5];
    const float* q_v = (const float*)d_in[6];
    const float* Wk  = (const float*)d_in[7];
    const float* bk  = (const float*)d_in[8];
    const float* k_s = (const float*)d_in[9];
    const float* k_o = (const float*)d_in[10];
    const float* k_m = (const float*)d_in[11];
    const float* k_v = (const float*)d_in[12];
    const float* Wv  = (const float*)d_in[13];
    const float* bv  = (const float*)d_in[14];
    const float* gam = (const float*)d_in[15];
    float* out = (float*)d_out;

    cudaFuncSetAttribute(attn, cudaFuncAttributeMaxDynamicSharedMemorySize, ASMEM);

    prep_wall<<<224, 256>>>(Wq, Wk, Wv);
    prep_bn<<<1, 32>>>(bq, q_s, q_o, q_m, q_v, bk, k_s, k_o, k_m, k_v);
    prep_pix<<<dim3(6, 232), 256>>>();
    x_pack<<<TOTPIX / 32, 256>>>(x);
    qkv_gemm<<<dim3(7, 24, 232), 256, QSMEM>>>(bv);
    combine_qk<<<dim3(96, 232), 256>>>();
    // shift regions (12..28) partition the image: write mode (out = x + delta)
    attn<<<dim3(24, 136), 256, ASMEM>>>(gam, x, out, 96, 0);
    // win regions (0..11): disjoint pixels within launch -> RMW
    attn<<<dim3(16, 96), 256, ASMEM>>>(gam, x, out, 0, 1);
}

// round 16
// speedup vs baseline: 1.1180x; 1.0007x over previous
#include <cuda_runtime.h>
#include <cuda_fp16.h>
#include <math.h>
#include <stdint.h>

// Problem constants (B=8, C=256, H=W=128, win_n=4, shift=16)
#define HW   16384
#define IMG  128
#define NREG 29
#define TOTPIX 229376
#define COUT 448        // 256 V + 96 Pq(3 taps x 32) + 96 Pk

typedef uint32_t u32;
typedef unsigned short u16;

__device__ __forceinline__ float f16r(float v) {
    return __half2float(__float2half_rn(v));
}
__device__ __forceinline__ u32 pack2(float e0, float e1) {   // e0 -> lo half
    __half2 h = __floats2half2_rn(e0, e1);
    return *reinterpret_cast<u32*>(&h);
}

// m16n8k16 fp16 MMA, fp32 accumulate
#define MMA_F16(d, a0, a1, a2, a3, b0, b1)                                           \
    asm volatile("mma.sync.aligned.m16n8k16.row.col.f32.f16.f16.f32 "                \
                 "{%0,%1,%2,%3},{%4,%5,%6,%7},{%8,%9},{%0,%1,%2,%3};"                \
                 : "+f"(d[0]), "+f"(d[1]), "+f"(d[2]), "+f"(d[3])                    \
                 : "r"(a0), "r"(a1), "r"(a2), "r"(a3), "r"(b0), "r"(b1))

__device__ __forceinline__ void cpa16(u32 dst, const u32* src) {
    asm volatile("cp.async.cg.shared.global [%0], [%1], 16;" :: "r"(dst), "l"(src));
}
#define CPA_COMMIT asm volatile("cp.async.commit_group;")
#define CPA_WAIT0  asm volatile("cp.async.wait_all;")

// Region tables: 12 win (rows 1..3 x cols 0..3), 9 shift-inner, 8 borders
__constant__ int c_h0[NREG] = {32,32,32,32, 64,64,64,64, 96,96,96,96,
                               16,16,16, 48,48,48, 80,80,80,
                               0,0,0, 16,16, 112,112,112};
__constant__ int c_w0[NREG] = {0,32,64,96, 0,32,64,96, 0,32,64,96,
                               16,48,80, 16,48,80, 16,48,80,
                               0,16,112, 0,112, 0,16,112};
__constant__ int c_Hr[NREG] = {32,32,32,32,32,32,32,32,32,32,32,32,
                               32,32,32,32,32,32,32,32,32,
                               16,16,16, 96,96, 16,16,16};
__constant__ int c_Wr[NREG] = {32,32,32,32,32,32,32,32,32,32,32,32,
                               32,32,32,32,32,32,32,32,32,
                               16,96,16, 16,16, 16,96,16};
__constant__ int c_N[NREG]  = {1024,1024,1024,1024,1024,1024,1024,1024,1024,1024,1024,1024,
                               1024,1024,1024,1024,1024,1024,1024,1024,1024,
                               256,1536,256, 1536,1536, 256,1536,256};
__constant__ int c_base[NREG] = {0,8192,16384,24576,32768,40960,49152,57344,65536,73728,81920,90112,
                                 98304,106496,114688,122880,131072,139264,147456,155648,163840,
                                 172032,174080,186368, 188416,200704, 212992,215040,227328};

// Scratch (__device__ globals)
static __device__ u32   g_W16h[COUT * 128];                  // [co][ci-pair] fp16x2 hi
static __device__ u32   g_W16l[COUT * 128];                  // lo residual
static __device__ u32   g_X16h[(size_t)TOTPIX * 128];        // [pix][ci-pair] fp16x2 hi
static __device__ u32   g_X16l[(size_t)TOTPIX * 128];        // lo residual
static __device__ u32   g_V16 [(size_t)TOTPIX * 128];        // [tile32][ch][key-pair]
static __device__ float g_PQK[(size_t)TOTPIX * 192];
static __device__ u32   g_Q16h[(size_t)TOTPIX * 16];         // [pix][d-pair]
static __device__ u32   g_Q16l[(size_t)TOTPIX * 16];
static __device__ u32   g_K16h[(size_t)TOTPIX * 16];
static __device__ u32   g_K16l[(size_t)TOTPIX * 16];
static __device__ int   g_pix[TOTPIX];
static __device__ float g_qsc[32], g_qof[32], g_ksc[32], g_kof[32];

// ---------------------------------------------------------------- prep kernels
__device__ __forceinline__ float wall_val(const float* Wq, const float* Wk,
                                          const float* Wv, int co, int ci) {
    if (co < 256) return Wv[co * 256 + ci];
    if (co < 352) { int t = (co - 256) >> 5, c8 = (co - 256) & 31;
                    return Wq[(c8 * 256 + ci) * 3 + t]; }
    { int t = (co - 352) >> 5, c8 = (co - 352) & 31;
      return Wk[(c8 * 256 + ci) * 3 + t]; }
}

__global__ void prep_wall(const float* __restrict__ Wq, const float* __restrict__ Wk,
                          const float* __restrict__ Wv) {
    int idx = blockIdx.x * 256 + threadIdx.x;
    if (idx >= COUT * 128) return;
    int co = idx >> 7, cp = idx & 127;
    float v0 = wall_val(Wq, Wk, Wv, co, 2 * cp);
    float v1 = wall_val(Wq, Wk, Wv, co, 2 * cp + 1);
    g_W16h[idx] = pack2(v0, v1);
    g_W16l[idx] = pack2(v0 - f16r(v0), v1 - f16r(v1));
}

__global__ void prep_bn(const float* bq, const float* qs, const float* qo, const float* qm, const float* qv,
                        const float* bk, const float* ks, const float* ko, const float* km, const float* kv) {
    int c = threadIdx.x;
    if (c >= 32) return;
    float sc = qs[c] * rsqrtf(qv[c] + 1e-5f);
    g_qsc[c] = sc;
    g_qof[c] = bq[c] * sc + qo[c] - qm[c] * sc;
    sc = ks[c] * rsqrtf(kv[c] + 1e-5f);
    g_ksc[c] = sc;
    g_kof[c] = bk[c] * sc + ko[c] - km[c] * sc;
}

__global__ void prep_pix() {
    int inst = blockIdx.y;
    int region = inst >> 3, b = inst & 7;
    int N = c_N[region];
    int n = blockIdx.x * 256 + threadIdx.x;
    if (n >= N) return;
    int Wr = c_Wr[region];
    int h = n / Wr, w = n - h * Wr;
    g_pix[c_base[region] + b * N + n] = b * (256 * HW) + (c_h0[region] + h) * IMG + c_w0[region] + w;
}

// ---------------- x_pack: one-time transpose-gather of x into fp16 hi/lo
__global__ __launch_bounds__(256) void x_pack(const float* __restrict__ x) {
    __shared__ u16 Xh[256 * 33];
    __shared__ u16 Xl[256 * 33];
    __shared__ int pas[32];
    int tid = threadIdx.x;
    int pixbase = blockIdx.x * 32;
    if (tid < 32) pas[tid] = g_pix[pixbase + tid];
    __syncthreads();
    int m = tid & 31, cw = tid >> 5;
#pragma unroll
    for (int r = 0; r < 32; r++) {
        int ci = cw + r * 8;
        float v = x[pas[m] + ci * HW];
        float h = f16r(v);
        Xh[ci * 33 + m] = __half_as_ushort(__float2half_rn(v));
        Xl[ci * 33 + m] = __half_as_ushort(__float2half_rn(v - h));
    }
    __syncthreads();
#pragma unroll
    for (int r = 0; r < 16; r++) {
        int idx = tid + r * 256;
        int mm = idx >> 7, cp = idx & 127;
        size_t o = (size_t)(pixbase + mm) * 128 + cp;
        g_X16h[o] = (u32)Xh[(2 * cp) * 33 + mm] | ((u32)Xh[(2 * cp + 1) * 33 + mm] << 16);
        g_X16l[o] = (u32)Xl[(2 * cp) * 33 + mm] | ((u32)Xl[(2 * cp + 1) * 33 + mm] << 16);
    }
}

// ---------------- QKV GEMM: [pix,256]@[256,448], cp.async pipeline, 1 sync/chunk
#define QAH 0
#define QAL 2560
#define QBH 5120
#define QBL 7680
#define QSMEM (10240 * 4)

__global__ __launch_bounds__(256) void qkv_gemm(const float* __restrict__ bv) {
    extern __shared__ u32 qsm[];
    u16* Vs16 = (u16*)qsm;         // epilogue alias (after k-loop + sync)
    u32 smb = (u32)__cvta_generic_to_shared(qsm);

    int inst = blockIdx.z;
    int region = inst >> 3, b = inst & 7;
    int N = c_N[region];
    int m0 = blockIdx.y * 64;
    if (m0 >= N) return;
    int pb = c_base[region] + b * N;
    int n0 = blockIdx.x * 64;
    bool vt = (n0 < 256);          // pure-V tile: plain fp16

    int tid = threadIdx.x;
    int lane = tid & 31, w = tid >> 5;
    int g = lane >> 2, t = lane & 3;
    int mt = w & 3, ntq = w >> 2;

    int prow = tid >> 2, pc4 = tid & 3;
    u32 sdst = (prow * 20 + pc4 * 4) * 4;
    size_t asrc0 = (size_t)(pb + m0 + prow) * 128 + pc4 * 4;
    size_t bsrc0 = (size_t)(n0 + prow) * 128 + pc4 * 4;

    float acc[4][4];
#pragma unroll
    for (int i = 0; i < 4; i++)
#pragma unroll
        for (int j = 0; j < 4; j++) acc[i][j] = 0.f;

    {
        cpa16(smb + QAH * 4 + sdst, &g_X16h[asrc0]);
        cpa16(smb + QBH * 4 + sdst, &g_W16h[bsrc0]);
        if (!vt) {
            cpa16(smb + QAL * 4 + sdst, &g_X16l[asrc0]);
            cpa16(smb + QBL * 4 + sdst, &g_W16l[bsrc0]);
        }
        CPA_COMMIT;
    }

    for (int it = 0; it < 8; it++) {         // 8 chunks of k=32
        int s = it & 1;
        CPA_WAIT0;
        __syncthreads();
        if (it + 1 < 8) {
            int s2 = (it + 1) & 1;
            size_t ko = (size_t)(it + 1) * 16;
            cpa16(smb + (QAH + s2 * 1280) * 4 + sdst, &g_X16h[asrc0 + ko]);
            cpa16(smb + (QBH + s2 * 1280) * 4 + sdst, &g_W16h[bsrc0 + ko]);
            if (!vt) {
                cpa16(smb + (QAL + s2 * 1280) * 4 + sdst, &g_X16l[asrc0 + ko]);
                cpa16(smb + (QBL + s2 * 1280) * 4 + sdst, &g_W16l[bsrc0 + ko]);
            }
            CPA_COMMIT;
        }
        u32* Ah = qsm + QAH + s * 1280;
        u32* Al = qsm + QAL + s * 1280;
        u32* Bh = qsm + QBH + s * 1280;
        u32* Bl = qsm + QBL + s * 1280;
#pragma unroll
        for (int kt = 0; kt < 2; kt++) {
            int ar = (mt * 16 + g) * 20 + kt * 8 + t;
            u32 ah0 = Ah[ar], ah1 = Ah[ar + 160], ah2 = Ah[ar + 4], ah3 = Ah[ar + 164];
#pragma unroll
            for (int ns = 0; ns < 4; ns++) {
                int nr = (ntq * 32 + ns * 8 + g) * 20 + kt * 8 + t;
                u32 bh0 = Bh[nr], bh1 = Bh[nr + 4];
                MMA_F16(acc[ns], ah0, ah1, ah2, ah3, bh0, bh1);
                if (!vt) {
                    u32 al0 = Al[ar], al1 = Al[ar + 160], al2 = Al[ar + 4], al3 = Al[ar + 164];
                    u32 bl0 = Bl[nr], bl1 = Bl[nr + 4];
                    MMA_F16(acc[ns], al0, al1, al2, al3, bh0, bh1);
                    MMA_F16(acc[ns], ah0, ah1, ah2, ah3, bl0, bl1);
                }
            }
        }
    }
    if (vt) {
        __syncthreads();
        int r0 = mt * 16 + g, r8 = r0 + 8;
#pragma unroll
        for (int ns = 0; ns < 4; ns++) {
            int co = n0 + ntq * 32 + ns * 8 + 2 * t;
            int chl = co - n0;
            float b0 = bv[co], b1 = bv[co + 1];
            Vs16[chl * 66 + r0]       = __half_as_ushort(__float2half_rn(acc[ns][0] + b0));
            Vs16[(chl + 1) * 66 + r0] = __half_as_ushort(__float2half_rn(acc[ns][1] + b1));
            Vs16[chl * 66 + r8]       = __half_as_ushort(__float2half_rn(acc[ns][2] + b0));
            Vs16[(chl + 1) * 66 + r8] = __half_as_ushort(__float2half_rn(acc[ns][3] + b1));
        }
        __syncthreads();
        int tile0 = (pb + m0) >> 5;
#pragma unroll
        for (int r = 0; r < 8; r++) {
            int idx = tid + r * 256;
            int chl = idx >> 5, kpl = idx & 31;
            u32 v = (u32)Vs16[chl * 66 + 2 * kpl] | ((u32)Vs16[chl * 66 + 2 * kpl + 1] << 16);
            int tileIdx = tile0 + (kpl >> 4);
            g_V16[(size_t)tileIdx * 4096 + (n0 + chl) * 16 + (kpl & 15)] = v;
        }
    } else {
#pragma unroll
        for (int ns = 0; ns < 4; ns++) {
            int co = n0 + ntq * 32 + ns * 8 + 2 * t;
            size_t mg  = (size_t)(pb + m0 + mt * 16 + g);
            size_t mg8 = mg + 8;
            int cp = co - 256;
            g_PQK[mg  * 192 + cp]     = acc[ns][0];
            g_PQK[mg  * 192 + cp + 1] = acc[ns][1];
            g_PQK[mg8 * 192 + cp]     = acc[ns][2];
            g_PQK[mg8 * 192 + cp + 1] = acc[ns][3];
        }
    }
}

// ------------- combine conv taps + BN + ReLU, split Q/K into fp16 hi/lo pairs
__global__ void combine_qk() {
    int inst = blockIdx.y;
    int region = inst >> 3, b = inst & 7;
    int N = c_N[region];
    int idx = blockIdx.x * 256 + threadIdx.x;
    int n = idx >> 4;
    if (n >= N) return;
    int cp = idx & 15, c0 = 2 * cp;
    int Wr = c_Wr[region], Hr = c_Hr[region];
    int pb = c_base[region] + b * N;
    int h = n / Wr, w = n - h * Wr;
    size_t rowp = (size_t)(pb + n) * 192;

    float2 q = *(float2*)&g_PQK[rowp + 32 + c0];
    if (w > 0)      { float2 a = *(float2*)&g_PQK[rowp - 192 + c0]; q.x += a.x; q.y += a.y; }
    if (w < Wr - 1) { float2 a = *(float2*)&g_PQK[rowp + 192 + 64 + c0]; q.x += a.x; q.y += a.y; }
    q.x = fmaxf(fmaf(q.x, g_qsc[c0], g_qof[c0]), 0.f);
    q.y = fmaxf(fmaf(q.y, g_qsc[c0 + 1], g_qof[c0 + 1]), 0.f);
    g_Q16h[(size_t)(pb + n) * 16 + cp] = pack2(q.x, q.y);
    g_Q16l[(size_t)(pb + n) * 16 + cp] = pack2(q.x - f16r(q.x), q.y - f16r(q.y));

    float2 k = *(float2*)&g_PQK[rowp + 96 + 32 + c0];
    if (h > 0)      { float2 a = *(float2*)&g_PQK[rowp - (size_t)Wr * 192 + 96 + c0]; k.x += a.x; k.y += a.y; }
    if (h < Hr - 1) { float2 a = *(float2*)&g_PQK[rowp + (size_t)Wr * 192 + 96 + 64 + c0]; k.x += a.x; k.y += a.y; }
    k.x = fmaxf(fmaf(k.x, g_ksc[c0], g_kof[c0]), 0.f);
    k.y = fmaxf(fmaf(k.y, g_ksc[c0 + 1], g_kof[c0 + 1]), 0.f);
    g_K16h[(size_t)(pb + n) * 16 + cp] = pack2(k.x, k.y);
    g_K16l[(size_t)(pb + n) * 16 + cp] = pack2(k.x - f16r(k.x), k.y - f16r(k.y));
}

// ------------------- fp16 flash attention, 64 q-rows x 64-key tiles
// PV warp map: 2 row-groups (32 rows) x 4 slabs (64 ch) -> each V fragment
// loaded once, reused by 2 row-tile MMAs (V crossbar traffic halved).
#define OKH 0          // 2 stages x 64x20
#define OKL 2560
#define OVS 5120       // 2 stages x 256x36
#define OP16 23552     // 64 x 36
#define OWM 25856      // wmax [2][64]
#define OWS 25984      // wsum [2][64]
#define OSTAT 26112    // rmax/rsum/rscale/pas 4x64
#define ASMEM (26368 * 4)

__global__ __launch_bounds__(256, 2) void attn(const float* __restrict__ gamma,
                                               const float* __restrict__ xin,
                                               float* __restrict__ out,
                                               int inst0, int mode) {
    extern __shared__ u32 sm32[];
    u32* Ps16 = sm32 + OP16;
    float* wmax = (float*)(sm32 + OWM);
    float* wsum = (float*)(sm32 + OWS);
    float* rmax = (float*)(sm32 + OSTAT);
    float* rsum = rmax + 64;
    float* rscale = rsum + 64;
    int* pas = (int*)(rscale + 64);
    float* stage = (float*)(sm32 + OVS);   // epilogue union over V buffers

    u32 smb = (u32)__cvta_generic_to_shared(sm32);

    int inst = inst0 + blockIdx.y;
    int region = inst >> 3, b = inst & 7;
    int N = c_N[region];
    int n0 = blockIdx.x * 64;
    if (n0 >= N) return;
    int pb = c_base[region] + b * N;

    int tid = threadIdx.x;
    int lane = tid & 31, w = tid >> 5;
    int g = lane >> 2, t = lane & 3;
    if (tid < 64) {
        rmax[tid] = -1e30f; rsum[tid] = 0.f;
        pas[tid] = g_pix[pb + n0 + tid];
    }

    int mt = w & 3, ntk = w >> 2;             // S mapping: rows mt*16, keys ntk*32
    int wm = w & 1, wslab = (w >> 1) * 64;    // PV: 32-row group wm, 64-ch slab
    int rowg = mt * 16 + g;

    // Q fragments hi/lo in registers (fixed per CTA)
    u32 aqh[2][4], aql[2][4];
    {
        size_t r0 = (size_t)(pb + n0 + rowg) * 16;
        size_t r8 = r0 + 128;
#pragma unroll
        for (int kt = 0; kt < 2; kt++) {
            int c = kt * 8 + t;
            aqh[kt][0] = g_Q16h[r0 + c];     aqh[kt][1] = g_Q16h[r8 + c];
            aqh[kt][2] = g_Q16h[r0 + c + 4]; aqh[kt][3] = g_Q16h[r8 + c + 4];
            aql[kt][0] = g_Q16l[r0 + c];     aql[kt][1] = g_Q16l[r8 + c];
            aql[kt][2] = g_Q16l[r0 + c + 4]; aql[kt][3] = g_Q16l[r8 + c + 4];
        }
    }

    // prefetch addressing
    int kidx = tid & 127;
    const u32* ksrc = (tid < 128) ? g_K16h : g_K16l;
    u32 kdst = (tid < 128) ? (u32)OKH : (u32)OKL;

    float acc[2][8][4];    // [row-tile rt][ch-tile nt][frag]
#pragma unroll
    for (int rt = 0; rt < 2; rt++)
#pragma unroll
        for (int nt = 0; nt < 8; nt++)
#pragma unroll
            for (int r = 0; r < 4; r++) acc[rt][nt][r] = 0.f;

    int nmt = N >> 6;
    // prologue: prefetch tile 0 into stage 0
    {
        int mb = pb;
#pragma unroll
        for (int r = 0; r < 2; r++) {
            int chunk = kidx + r * 128;
            int krow = chunk >> 2, kc4 = chunk & 3;
            cpa16(smb + (kdst + krow * 20 + kc4 * 4) * 4, &ksrc[(size_t)(mb + krow) * 16 + kc4 * 4]);
        }
        size_t vbase = (size_t)(mb >> 5) * 4096;
#pragma unroll
        for (int r = 0; r < 8; r++) {
            int idx = tid + r * 256;
            int ch = idx >> 3, sub = idx & 7;
            int half = sub >> 2, c4 = sub & 3;
            cpa16(smb + (OVS + ch * 36 + half * 16 + c4 * 4) * 4,
                  &g_V16[vbase + (size_t)half * 4096 + ch * 16 + c4 * 4]);
        }
        CPA_COMMIT;
    }

    for (int it = 0; it < nmt; it++) {
        int s = it & 1;
        CPA_WAIT0;
        __syncthreads();                       // B: stage s visible; s^1 + Ps16 free
        if (it + 1 < nmt) {
            int mb = pb + (it + 1) * 64;
            int s2 = (it + 1) & 1;
#pragma unroll
            for (int r = 0; r < 2; r++) {
                int chunk = kidx + r * 128;
                int krow = chunk >> 2, kc4 = chunk & 3;
                cpa16(smb + (kdst + s2 * 1280 + krow * 20 + kc4 * 4) * 4,
                      &ksrc[(size_t)(mb + krow) * 16 + kc4 * 4]);
            }
            size_t vbase = (size_t)(mb >> 5) * 4096;
#pragma unroll
            for (int r = 0; r < 8; r++) {
                int idx = tid + r * 256;
                int ch = idx >> 3, sub = idx & 7;
                int half = sub >> 2, c4 = sub & 3;
                cpa16(smb + (OVS + s2 * 9216 + ch * 36 + half * 16 + c4 * 4) * 4,
                      &g_V16[vbase + (size_t)half * 4096 + ch * 16 + c4 * 4]);
            }
            CPA_COMMIT;
        }
        u32* Kh = sm32 + OKH + s * 1280;
        u32* Kl = sm32 + OKL + s * 1280;
        u32* Vs = sm32 + OVS + s * 9216;

        // ---- S: split-fp16, warp does 16 rows x 32 keys (registers)
        float sacc[4][4];
#pragma unroll
        for (int i = 0; i < 4; i++)
#pragma unroll
            for (int j = 0; j < 4; j++) sacc[i][j] = 0.f;
#pragma unroll
        for (int kt = 0; kt < 2; kt++) {
            u32 ah0 = aqh[kt][0], ah1 = aqh[kt][1], ah2 = aqh[kt][2], ah3 = aqh[kt][3];
            u32 al0 = aql[kt][0], al1 = aql[kt][1], al2 = aql[kt][2], al3 = aql[kt][3];
#pragma unroll
            for (int sub = 0; sub < 4; sub++) {
                int kr = (ntk * 32 + sub * 8 + g) * 20 + kt * 8 + t;
                u32 bh0 = Kh[kr], bh1 = Kh[kr + 4];
                u32 bl0 = Kl[kr], bl1 = Kl[kr + 4];
                MMA_F16(sacc[sub], ah0, ah1, ah2, ah3, bh0, bh1);
                MMA_F16(sacc[sub], al0, al1, al2, al3, bh0, bh1);
                MMA_F16(sacc[sub], ah0, ah1, ah2, ah3, bl0, bl1);
            }
        }
        // ---- softmax phase A: warp-local row max over 32 keys
        float m0 = fmaxf(fmaxf(sacc[0][0], sacc[0][1]), fmaxf(sacc[1][0], sacc[1][1]));
        m0 = fmaxf(m0, fmaxf(fmaxf(sacc[2][0], sacc[2][1]), fmaxf(sacc[3][0], sacc[3][1])));
        float m1 = fmaxf(fmaxf(sacc[0][2], sacc[0][3]), fmaxf(sacc[1][2], sacc[1][3]));
        m1 = fmaxf(m1, fmaxf(fmaxf(sacc[2][2], sacc[2][3]), fmaxf(sacc[3][2], sacc[3][3])));
        m0 = fmaxf(m0, __shfl_xor_sync(0xffffffffu, m0, 1));
        m0 = fmaxf(m0, __shfl_xor_sync(0xffffffffu, m0, 2));
        m1 = fmaxf(m1, __shfl_xor_sync(0xffffffffu, m1, 1));
        m1 = fmaxf(m1, __shfl_xor_sync(0xffffffffu, m1, 2));
        float rm0 = rmax[rowg], rm1 = rmax[rowg + 8];
        if (t == 0) {
            wmax[ntk * 64 + rowg]     = m0;
            wmax[ntk * 64 + rowg + 8] = m1;
        }
        __syncthreads();                       // C: wmax visible
        // ---- softmax phase B: exp in registers, pack to Ps16
        float nm0 = fmaxf(rm0, fmaxf(wmax[rowg], wmax[64 + rowg]));
        float nm1 = fmaxf(rm1, fmaxf(wmax[rowg + 8], wmax[64 + rowg + 8]));
        float s0 = 0.f, s1 = 0.f;
#pragma unroll
        for (int sub = 0; sub < 4; sub++) {
            float p00 = __expf(sacc[sub][0] - nm0);
            float p01 = __expf(sacc[sub][1] - nm0);
            float p10 = __expf(sacc[sub][2] - nm1);
            float p11 = __expf(sacc[sub][3] - nm1);
            s0 += p00 + p01; s1 += p10 + p11;
            int kp = ntk * 16 + sub * 4 + t;
            Ps16[rowg * 36 + kp]       = pack2(p00, p01);
            Ps16[(rowg + 8) * 36 + kp] = pack2(p10, p11);
        }
        s0 += __shfl_xor_sync(0xffffffffu, s0, 1);
        s0 += __shfl_xor_sync(0xffffffffu, s0, 2);
        s1 += __shfl_xor_sync(0xffffffffu, s1, 1);
        s1 += __shfl_xor_sync(0xffffffffu, s1, 2);
        if (t == 0) {
            wsum[ntk * 64 + rowg]     = s0;
            wsum[ntk * 64 + rowg + 8] = s1;
            if (ntk == 0) {
                rscale[rowg]     = __expf(rm0 - nm0);
                rscale[rowg + 8] = __expf(rm1 - nm1);
                rmax[rowg] = nm0; rmax[rowg + 8] = nm1;
            }
        }
        __syncthreads();                       // D: Ps16 + rscale + wsum visible
        // ---- PV: rescale + fp16 MMA (warp: 32 rows x 64 ch, 64 keys)
        {
#pragma unroll
            for (int rt = 0; rt < 2; rt++) {
                float sc0 = rscale[wm * 32 + rt * 16 + g];
                float sc1 = rscale[wm * 32 + rt * 16 + g + 8];
#pragma unroll
                for (int nt = 0; nt < 8; nt++) {
                    acc[rt][nt][0] *= sc0; acc[rt][nt][1] *= sc0;
                    acc[rt][nt][2] *= sc1; acc[rt][nt][3] *= sc1;
                }
            }
#pragma unroll
            for (int kt = 0; kt < 4; kt++) {
                u32 pa[2][4];
#pragma unroll
                for (int rt = 0; rt < 2; rt++) {
                    int pr = (wm * 32 + rt * 16 + g) * 36 + kt * 8 + t;
                    pa[rt][0] = Ps16[pr];       pa[rt][1] = Ps16[pr + 288];
                    pa[rt][2] = Ps16[pr + 4];   pa[rt][3] = Ps16[pr + 292];
                }
#pragma unroll
                for (int nt = 0; nt < 8; nt++) {
                    int vr = (wslab + nt * 8 + g) * 36 + kt * 8 + t;
                    u32 b0 = Vs[vr], b1 = Vs[vr + 4];   // loaded once, used twice
                    MMA_F16(acc[0][nt], pa[0][0], pa[0][1], pa[0][2], pa[0][3], b0, b1);
                    MMA_F16(acc[1][nt], pa[1][0], pa[1][1], pa[1][2], pa[1][3], b0, b1);
                }
            }
        }
        // running-sum update (rsum read only at epilogue)
        if (w < 4 && lane < 16) {
            int row = w * 16 + lane;
            rsum[row] = rsum[row] * rscale[row] + wsum[row] + wsum[64 + row];
        }
    }
    // epilogue: two passes of 32 rows staged, then coalesced write/RMW
    float gm = 0.5f * gamma[0];
#pragma unroll
    for (int pass = 0; pass < 2; pass++) {
        __syncthreads();
        if (wm == pass) {
#pragma unroll
            for (int rt = 0; rt < 2; rt++) {
                float f0 = gm / rsum[wm * 32 + rt * 16 + g];
                float f1 = gm / rsum[wm * 32 + rt * 16 + g + 8];
                int row0 = rt * 16 + g;
                int r0 = row0 * 264 + wslab + 2 * t;
                int r8 = (row0 + 8) * 264 + wslab + 2 * t;
#pragma unroll
                for (int nt = 0; nt < 8; nt++) {
                    stage[r0 + nt * 8]     = acc[rt][nt][0] * f0;
                    stage[r0 + nt * 8 + 1] = acc[rt][nt][1] * f0;
                    stage[r8 + nt * 8]     = acc[rt][nt][2] * f1;
                    stage[r8 + nt * 8 + 1] = acc[rt][nt][3] * f1;
                }
            }
        }
        __syncthreads();
        int tn = tid & 7, tc = tid >> 3;
#pragma unroll
        for (int i = 0; i < 4; i++) {
            int row = tn + 8 * i;
            int pa = pas[pass * 32 + row];
#pragma unroll
            for (int j = 0; j < 8; j++) {
                int c = tc * 8 + j;
                float vv = stage[row * 264 + c];
                if (mode) out[pa + c * HW] += vv;
                else      out[pa + c * HW] = xin[pa + c * HW] + vv;
            }
        }
    }
}

// ---------------------------------------------------------------- launcher
extern "C" void kernel_launch(void* const* d_in, const int* in_sizes, int n_in,
                              void* d_out, int out_size) {
    const float* x   = (const float*)d_in[0];
    const float* Wq  = (const float*)d_in[1];
    const float* bq  = (const float*)d_in[2];
    const float* q_s = (const float*)d_in[3];
    const float* q_o = (const float*)d_in[4];
    const float* q_m = (const float*)d_in[5];
    const float* q_v = (const float*)d_in[6];
    const float* Wk  = (const float*)d_in[7];
    const float* bk  = (const float*)d_in[8];
    const float* k_s = (const float*)d_in[9];
    const float* k_o = (const float*)d_in[10];
    const float* k_m = (const float*)d_in[11];
    const float* k_v = (const float*)d_in[12];
    const float* Wv  = (const float*)d_in[13];
    const float* bv  = (const float*)d_in[14];
    const float* gam = (const float*)d_in[15];
    float* out = (float*)d_out;

    cudaFuncSetAttribute(attn, cudaFuncAttributeMaxDynamicSharedMemorySize, ASMEM);

    prep_wall<<<224, 256>>>(Wq, Wk, Wv);
    prep_bn<<<1, 32>>>(bq, q_s, q_o, q_m, q_v, bk, k_s, k_o, k_m, k_v);
    prep_pix<<<dim3(6, 232), 256>>>();
    x_pack<<<TOTPIX / 32, 256>>>(x);
    qkv_gemm<<<dim3(7, 24, 232), 256, QSMEM>>>(bv);
    combine_qk<<<dim3(96, 232), 256>>>();
    // shift regions (12..28) partition the image: write mode (out = x + delta)
    attn<<<dim3(24, 136), 256, ASMEM>>>(gam, x, out, 96, 0);
    // win regions (0..11): disjoint pixels within launch -> RMW
    attn<<<dim3(16, 96), 256, ASMEM>>>(gam, x, out, 0, 1);
}

// round 17
// speedup vs baseline: 1.1741x; 1.0502x over previous
#include <cuda_runtime.h>
#include <cuda_fp16.h>
#include <math.h>
#include <stdint.h>

// Problem constants (B=8, C=256, H=W=128, win_n=4, shift=16)
#define HW   16384
#define IMG  128
#define NREG 29
#define TOTPIX 229376
#define COUT 448        // 256 V + 96 Pq(3 taps x 32) + 96 Pk

typedef uint32_t u32;
typedef unsigned short u16;

__device__ __forceinline__ float f16r(float v) {
    return __half2float(__float2half_rn(v));
}
__device__ __forceinline__ u32 pack2(float e0, float e1) {   // e0 -> lo half
    __half2 h = __floats2half2_rn(e0, e1);
    return *reinterpret_cast<u32*>(&h);
}

// m16n8k16 fp16 MMA, fp32 accumulate
#define MMA_F16(d, a0, a1, a2, a3, b0, b1)                                           \
    asm volatile("mma.sync.aligned.m16n8k16.row.col.f32.f16.f16.f32 "                \
                 "{%0,%1,%2,%3},{%4,%5,%6,%7},{%8,%9},{%0,%1,%2,%3};"                \
                 : "+f"(d[0]), "+f"(d[1]), "+f"(d[2]), "+f"(d[3])                    \
                 : "r"(a0), "r"(a1), "r"(a2), "r"(a3), "r"(b0), "r"(b1))

__device__ __forceinline__ void cpa16(u32 dst, const u32* src) {
    asm volatile("cp.async.cg.shared.global [%0], [%1], 16;" :: "r"(dst), "l"(src));
}
#define CPA_COMMIT asm volatile("cp.async.commit_group;")
#define CPA_WAIT0  asm volatile("cp.async.wait_all;")

// Region tables: 12 win (rows 1..3 x cols 0..3), 9 shift-inner, 8 borders
__constant__ int c_h0[NREG] = {32,32,32,32, 64,64,64,64, 96,96,96,96,
                               16,16,16, 48,48,48, 80,80,80,
                               0,0,0, 16,16, 112,112,112};
__constant__ int c_w0[NREG] = {0,32,64,96, 0,32,64,96, 0,32,64,96,
                               16,48,80, 16,48,80, 16,48,80,
                               0,16,112, 0,112, 0,16,112};
__constant__ int c_Hr[NREG] = {32,32,32,32,32,32,32,32,32,32,32,32,
                               32,32,32,32,32,32,32,32,32,
                               16,16,16, 96,96, 16,16,16};
__constant__ int c_Wr[NREG] = {32,32,32,32,32,32,32,32,32,32,32,32,
                               32,32,32,32,32,32,32,32,32,
                               16,96,16, 16,16, 16,96,16};
__constant__ int c_N[NREG]  = {1024,1024,1024,1024,1024,1024,1024,1024,1024,1024,1024,1024,
                               1024,1024,1024,1024,1024,1024,1024,1024,1024,
                               256,1536,256, 1536,1536, 256,1536,256};
__constant__ int c_base[NREG] = {0,8192,16384,24576,32768,40960,49152,57344,65536,73728,81920,90112,
                                 98304,106496,114688,122880,131072,139264,147456,155648,163840,
                                 172032,174080,186368, 188416,200704, 212992,215040,227328};

// Scratch (__device__ globals)
static __device__ u32   g_W16h[COUT * 128];                  // [co][ci-pair] fp16x2 hi
static __device__ u32   g_W16l[COUT * 128];                  // lo residual
static __device__ u32   g_X16h[(size_t)TOTPIX * 128];        // [pix][ci-pair] fp16x2 hi
static __device__ u32   g_X16l[(size_t)TOTPIX * 128];        // lo residual
static __device__ u32   g_V16 [(size_t)TOTPIX * 128];        // [tile32][ch][key-pair]
static __device__ float g_PQK[(size_t)TOTPIX * 192];
static __device__ u32   g_Q16h[(size_t)TOTPIX * 16];         // [pix][d-pair]
static __device__ u32   g_Q16l[(size_t)TOTPIX * 16];
static __device__ u32   g_K16h[(size_t)TOTPIX * 16];         // K plain fp16 (no lo)
static __device__ int   g_pix[TOTPIX];
static __device__ float g_qsc[32], g_qof[32], g_ksc[32], g_kof[32];

// ---------------------------------------------------------------- prep kernels
__device__ __forceinline__ float wall_val(const float* Wq, const float* Wk,
                                          const float* Wv, int co, int ci) {
    if (co < 256) return Wv[co * 256 + ci];
    if (co < 352) { int t = (co - 256) >> 5, c8 = (co - 256) & 31;
                    return Wq[(c8 * 256 + ci) * 3 + t]; }
    { int t = (co - 352) >> 5, c8 = (co - 352) & 31;
      return Wk[(c8 * 256 + ci) * 3 + t]; }
}

__global__ void prep_wall(const float* __restrict__ Wq, const float* __restrict__ Wk,
                          const float* __restrict__ Wv) {
    int idx = blockIdx.x * 256 + threadIdx.x;
    if (idx >= COUT * 128) return;
    int co = idx >> 7, cp = idx & 127;
    float v0 = wall_val(Wq, Wk, Wv, co, 2 * cp);
    float v1 = wall_val(Wq, Wk, Wv, co, 2 * cp + 1);
    g_W16h[idx] = pack2(v0, v1);
    g_W16l[idx] = pack2(v0 - f16r(v0), v1 - f16r(v1));
}

__global__ void prep_bn(const float* bq, const float* qs, const float* qo, const float* qm, const float* qv,
                        const float* bk, const float* ks, const float* ko, const float* km, const float* kv) {
    int c = threadIdx.x;
    if (c >= 32) return;
    float sc = qs[c] * rsqrtf(qv[c] + 1e-5f);
    g_qsc[c] = sc;
    g_qof[c] = bq[c] * sc + qo[c] - qm[c] * sc;
    sc = ks[c] * rsqrtf(kv[c] + 1e-5f);
    g_ksc[c] = sc;
    g_kof[c] = bk[c] * sc + ko[c] - km[c] * sc;
}

__global__ void prep_pix() {
    int inst = blockIdx.y;
    int region = inst >> 3, b = inst & 7;
    int N = c_N[region];
    int n = blockIdx.x * 256 + threadIdx.x;
    if (n >= N) return;
    int Wr = c_Wr[region];
    int h = n / Wr, w = n - h * Wr;
    g_pix[c_base[region] + b * N + n] = b * (256 * HW) + (c_h0[region] + h) * IMG + c_w0[region] + w;
}

// ---------------- x_pack: one-time transpose-gather of x into fp16 hi/lo
__global__ __launch_bounds__(256) void x_pack(const float* __restrict__ x) {
    __shared__ u16 Xh[256 * 33];
    __shared__ u16 Xl[256 * 33];
    __shared__ int pas[32];
    int tid = threadIdx.x;
    int pixbase = blockIdx.x * 32;
    if (tid < 32) pas[tid] = g_pix[pixbase + tid];
    __syncthreads();
    int m = tid & 31, cw = tid >> 5;
#pragma unroll
    for (int r = 0; r < 32; r++) {
        int ci = cw + r * 8;
        float v = x[pas[m] + ci * HW];
        float h = f16r(v);
        Xh[ci * 33 + m] = __half_as_ushort(__float2half_rn(v));
        Xl[ci * 33 + m] = __half_as_ushort(__float2half_rn(v - h));
    }
    __syncthreads();
#pragma unroll
    for (int r = 0; r < 16; r++) {
        int idx = tid + r * 256;
        int mm = idx >> 7, cp = idx & 127;
        size_t o = (size_t)(pixbase + mm) * 128 + cp;
        g_X16h[o] = (u32)Xh[(2 * cp) * 33 + mm] | ((u32)Xh[(2 * cp + 1) * 33 + mm] << 16);
        g_X16l[o] = (u32)Xl[(2 * cp) * 33 + mm] | ((u32)Xl[(2 * cp + 1) * 33 + mm] << 16);
    }
}

// ---------------- QKV GEMM: [pix,256]@[256,448], cp.async pipeline, 1 sync/chunk
#define QAH 0
#define QAL 2560
#define QBH 5120
#define QBL 7680
#define QSMEM (10240 * 4)

__global__ __launch_bounds__(256) void qkv_gemm(const float* __restrict__ bv) {
    extern __shared__ u32 qsm[];
    u16* Vs16 = (u16*)qsm;         // epilogue alias (after k-loop + sync)
    u32 smb = (u32)__cvta_generic_to_shared(qsm);

    int inst = blockIdx.z;
    int region = inst >> 3, b = inst & 7;
    int N = c_N[region];
    int m0 = blockIdx.y * 64;
    if (m0 >= N) return;
    int pb = c_base[region] + b * N;
    int n0 = blockIdx.x * 64;
    bool vt = (n0 < 256);          // pure-V tile: plain fp16

    int tid = threadIdx.x;
    int lane = tid & 31, w = tid >> 5;
    int g = lane >> 2, t = lane & 3;
    int mt = w & 3, ntq = w >> 2;

    int prow = tid >> 2, pc4 = tid & 3;
    u32 sdst = (prow * 20 + pc4 * 4) * 4;
    size_t asrc0 = (size_t)(pb + m0 + prow) * 128 + pc4 * 4;
    size_t bsrc0 = (size_t)(n0 + prow) * 128 + pc4 * 4;

    float acc[4][4];
#pragma unroll
    for (int i = 0; i < 4; i++)
#pragma unroll
        for (int j = 0; j < 4; j++) acc[i][j] = 0.f;

    {
        cpa16(smb + QAH * 4 + sdst, &g_X16h[asrc0]);
        cpa16(smb + QBH * 4 + sdst, &g_W16h[bsrc0]);
        if (!vt) {
            cpa16(smb + QAL * 4 + sdst, &g_X16l[asrc0]);
            cpa16(smb + QBL * 4 + sdst, &g_W16l[bsrc0]);
        }
        CPA_COMMIT;
    }

    for (int it = 0; it < 8; it++) {         // 8 chunks of k=32
        int s = it & 1;
        CPA_WAIT0;
        __syncthreads();
        if (it + 1 < 8) {
            int s2 = (it + 1) & 1;
            size_t ko = (size_t)(it + 1) * 16;
            cpa16(smb + (QAH + s2 * 1280) * 4 + sdst, &g_X16h[asrc0 + ko]);
            cpa16(smb + (QBH + s2 * 1280) * 4 + sdst, &g_W16h[bsrc0 + ko]);
            if (!vt) {
                cpa16(smb + (QAL + s2 * 1280) * 4 + sdst, &g_X16l[asrc0 + ko]);
                cpa16(smb + (QBL + s2 * 1280) * 4 + sdst, &g_W16l[bsrc0 + ko]);
            }
            CPA_COMMIT;
        }
        u32* Ah = qsm + QAH + s * 1280;
        u32* Al = qsm + QAL + s * 1280;
        u32* Bh = qsm + QBH + s * 1280;
        u32* Bl = qsm + QBL + s * 1280;
#pragma unroll
        for (int kt = 0; kt < 2; kt++) {
            int ar = (mt * 16 + g) * 20 + kt * 8 + t;
            u32 ah0 = Ah[ar], ah1 = Ah[ar + 160], ah2 = Ah[ar + 4], ah3 = Ah[ar + 164];
#pragma unroll
            for (int ns = 0; ns < 4; ns++) {
                int nr = (ntq * 32 + ns * 8 + g) * 20 + kt * 8 + t;
                u32 bh0 = Bh[nr], bh1 = Bh[nr + 4];
                MMA_F16(acc[ns], ah0, ah1, ah2, ah3, bh0, bh1);
                if (!vt) {
                    u32 al0 = Al[ar], al1 = Al[ar + 160], al2 = Al[ar + 4], al3 = Al[ar + 164];
                    u32 bl0 = Bl[nr], bl1 = Bl[nr + 4];
                    MMA_F16(acc[ns], al0, al1, al2, al3, bh0, bh1);
                    MMA_F16(acc[ns], ah0, ah1, ah2, ah3, bl0, bl1);
                }
            }
        }
    }
    if (vt) {
        __syncthreads();
        int r0 = mt * 16 + g, r8 = r0 + 8;
#pragma unroll
        for (int ns = 0; ns < 4; ns++) {
            int co = n0 + ntq * 32 + ns * 8 + 2 * t;
            int chl = co - n0;
            float b0 = bv[co], b1 = bv[co + 1];
            Vs16[chl * 66 + r0]       = __half_as_ushort(__float2half_rn(acc[ns][0] + b0));
            Vs16[(chl + 1) * 66 + r0] = __half_as_ushort(__float2half_rn(acc[ns][1] + b1));
            Vs16[chl * 66 + r8]       = __half_as_ushort(__float2half_rn(acc[ns][2] + b0));
            Vs16[(chl + 1) * 66 + r8] = __half_as_ushort(__float2half_rn(acc[ns][3] + b1));
        }
        __syncthreads();
        int tile0 = (pb + m0) >> 5;
#pragma unroll
        for (int r = 0; r < 8; r++) {
            int idx = tid + r * 256;
            int chl = idx >> 5, kpl = idx & 31;
            u32 v = (u32)Vs16[chl * 66 + 2 * kpl] | ((u32)Vs16[chl * 66 + 2 * kpl + 1] << 16);
            int tileIdx = tile0 + (kpl >> 4);
            g_V16[(size_t)tileIdx * 4096 + (n0 + chl) * 16 + (kpl & 15)] = v;
        }
    } else {
#pragma unroll
        for (int ns = 0; ns < 4; ns++) {
            int co = n0 + ntq * 32 + ns * 8 + 2 * t;
            size_t mg  = (size_t)(pb + m0 + mt * 16 + g);
            size_t mg8 = mg + 8;
            int cp = co - 256;
            g_PQK[mg  * 192 + cp]     = acc[ns][0];
            g_PQK[mg  * 192 + cp + 1] = acc[ns][1];
            g_PQK[mg8 * 192 + cp]     = acc[ns][2];
            g_PQK[mg8 * 192 + cp + 1] = acc[ns][3];
        }
    }
}

// ------------- combine conv taps + BN + ReLU; Q hi/lo, K plain fp16
__global__ void combine_qk() {
    int inst = blockIdx.y;
    int region = inst >> 3, b = inst & 7;
    int N = c_N[region];
    int idx = blockIdx.x * 256 + threadIdx.x;
    int n = idx >> 4;
    if (n >= N) return;
    int cp = idx & 15, c0 = 2 * cp;
    int Wr = c_Wr[region], Hr = c_Hr[region];
    int pb = c_base[region] + b * N;
    int h = n / Wr, w = n - h * Wr;
    size_t rowp = (size_t)(pb + n) * 192;

    float2 q = *(float2*)&g_PQK[rowp + 32 + c0];
    if (w > 0)      { float2 a = *(float2*)&g_PQK[rowp - 192 + c0]; q.x += a.x; q.y += a.y; }
    if (w < Wr - 1) { float2 a = *(float2*)&g_PQK[rowp + 192 + 64 + c0]; q.x += a.x; q.y += a.y; }
    q.x = fmaxf(fmaf(q.x, g_qsc[c0], g_qof[c0]), 0.f);
    q.y = fmaxf(fmaf(q.y, g_qsc[c0 + 1], g_qof[c0 + 1]), 0.f);
    g_Q16h[(size_t)(pb + n) * 16 + cp] = pack2(q.x, q.y);
    g_Q16l[(size_t)(pb + n) * 16 + cp] = pack2(q.x - f16r(q.x), q.y - f16r(q.y));

    float2 k = *(float2*)&g_PQK[rowp + 96 + 32 + c0];
    if (h > 0)      { float2 a = *(float2*)&g_PQK[rowp - (size_t)Wr * 192 + 96 + c0]; k.x += a.x; k.y += a.y; }
    if (h < Hr - 1) { float2 a = *(float2*)&g_PQK[rowp + (size_t)Wr * 192 + 96 + 64 + c0]; k.x += a.x; k.y += a.y; }
    k.x = fmaxf(fmaf(k.x, g_ksc[c0], g_kof[c0]), 0.f);
    k.y = fmaxf(fmaf(k.y, g_ksc[c0 + 1], g_kof[c0 + 1]), 0.f);
    g_K16h[(size_t)(pb + n) * 16 + cp] = pack2(k.x, k.y);
}

// ------------------- fp16 flash attention, 64 q-rows x 64-key tiles
// S = (q_h + q_l) · k_fp16 (2 MMAs; K-lo eliminated). PV: V frag reuse x2.
#define OKH 0          // 2 stages x 64x20 (K hi only)
#define OVS 2560       // 2 stages x 256x36
#define OP16 20992     // 64 x 36
#define OWM 23296      // wmax [2][64]
#define OWS 23424      // wsum [2][64]
#define OSTAT 23552    // rmax/rsum/rscale/pas 4x64
#define ASMEM ((23552 + 256) * 4)

__global__ __launch_bounds__(256, 2) void attn(const float* __restrict__ gamma,
                                               const float* __restrict__ xin,
                                               float* __restrict__ out,
                                               int inst0, int mode) {
    extern __shared__ u32 sm32[];
    u32* Ps16 = sm32 + OP16;
    float* wmax = (float*)(sm32 + OWM);
    float* wsum = (float*)(sm32 + OWS);
    float* rmax = (float*)(sm32 + OSTAT);
    float* rsum = rmax + 64;
    float* rscale = rsum + 64;
    int* pas = (int*)(rscale + 64);
    float* stage = (float*)(sm32 + OVS);   // epilogue union over V buffers

    u32 smb = (u32)__cvta_generic_to_shared(sm32);

    int inst = inst0 + blockIdx.y;
    int region = inst >> 3, b = inst & 7;
    int N = c_N[region];
    int n0 = blockIdx.x * 64;
    if (n0 >= N) return;
    int pb = c_base[region] + b * N;

    int tid = threadIdx.x;
    int lane = tid & 31, w = tid >> 5;
    int g = lane >> 2, t = lane & 3;
    if (tid < 64) {
        rmax[tid] = -1e30f; rsum[tid] = 0.f;
        pas[tid] = g_pix[pb + n0 + tid];
    }

    int mt = w & 3, ntk = w >> 2;             // S mapping: rows mt*16, keys ntk*32
    int wm = w & 1, wslab = (w >> 1) * 64;    // PV: 32-row group wm, 64-ch slab
    int rowg = mt * 16 + g;

    // Q fragments hi/lo in registers (fixed per CTA)
    u32 aqh[2][4], aql[2][4];
    {
        size_t r0 = (size_t)(pb + n0 + rowg) * 16;
        size_t r8 = r0 + 128;
#pragma unroll
        for (int kt = 0; kt < 2; kt++) {
            int c = kt * 8 + t;
            aqh[kt][0] = g_Q16h[r0 + c];     aqh[kt][1] = g_Q16h[r8 + c];
            aqh[kt][2] = g_Q16h[r0 + c + 4]; aqh[kt][3] = g_Q16h[r8 + c + 4];
            aql[kt][0] = g_Q16l[r0 + c];     aql[kt][1] = g_Q16l[r8 + c];
            aql[kt][2] = g_Q16l[r0 + c + 4]; aql[kt][3] = g_Q16l[r8 + c + 4];
        }
    }

    // prefetch addressing: 256 threads cover 64 K rows x 4 float4
    int krow = tid >> 2, kc4 = tid & 3;
    u32 kdoff = (krow * 20 + kc4 * 4) * 4;     // byte offset in a K stage

    float acc[2][8][4];    // [row-tile rt][ch-tile nt][frag]
#pragma unroll
    for (int rt = 0; rt < 2; rt++)
#pragma unroll
        for (int nt = 0; nt < 8; nt++)
#pragma unroll
            for (int r = 0; r < 4; r++) acc[rt][nt][r] = 0.f;

    int nmt = N >> 6;
    // prologue: prefetch tile 0 into stage 0
    {
        int mb = pb;
        cpa16(smb + OKH * 4 + kdoff, &g_K16h[(size_t)(mb + krow) * 16 + kc4 * 4]);
        size_t vbase = (size_t)(mb >> 5) * 4096;
#pragma unroll
        for (int r = 0; r < 8; r++) {
            int idx = tid + r * 256;
            int ch = idx >> 3, sub = idx & 7;
            int half = sub >> 2, c4 = sub & 3;
            cpa16(smb + (OVS + ch * 36 + half * 16 + c4 * 4) * 4,
                  &g_V16[vbase + (size_t)half * 4096 + ch * 16 + c4 * 4]);
        }
        CPA_COMMIT;
    }

    for (int it = 0; it < nmt; it++) {
        int s = it & 1;
        CPA_WAIT0;
        __syncthreads();                       // B: stage s visible; s^1 + Ps16 free
        if (it + 1 < nmt) {
            int mb = pb + (it + 1) * 64;
            int s2 = (it + 1) & 1;
            cpa16(smb + (OKH + s2 * 1280) * 4 + kdoff,
                  &g_K16h[(size_t)(mb + krow) * 16 + kc4 * 4]);
            size_t vbase = (size_t)(mb >> 5) * 4096;
#pragma unroll
            for (int r = 0; r < 8; r++) {
                int idx = tid + r * 256;
                int ch = idx >> 3, sub = idx & 7;
                int half = sub >> 2, c4 = sub & 3;
                cpa16(smb + (OVS + s2 * 9216 + ch * 36 + half * 16 + c4 * 4) * 4,
                      &g_V16[vbase + (size_t)half * 4096 + ch * 16 + c4 * 4]);
            }
            CPA_COMMIT;
        }
        u32* Kh = sm32 + OKH + s * 1280;
        u32* Vs = sm32 + OVS + s * 9216;

        // ---- S: (q_h + q_l)·k_h, warp does 16 rows x 32 keys (registers)
        float sacc[4][4];
#pragma unroll
        for (int i = 0; i < 4; i++)
#pragma unroll
            for (int j = 0; j < 4; j++) sacc[i][j] = 0.f;
#pragma unroll
        for (int kt = 0; kt < 2; kt++) {
            u32 ah0 = aqh[kt][0], ah1 = aqh[kt][1], ah2 = aqh[kt][2], ah3 = aqh[kt][3];
            u32 al0 = aql[kt][0], al1 = aql[kt][1], al2 = aql[kt][2], al3 = aql[kt][3];
#pragma unroll
            for (int sub = 0; sub < 4; sub++) {
                int kr = (ntk * 32 + sub * 8 + g) * 20 + kt * 8 + t;
                u32 bh0 = Kh[kr], bh1 = Kh[kr + 4];
                MMA_F16(sacc[sub], ah0, ah1, ah2, ah3, bh0, bh1);
                MMA_F16(sacc[sub], al0, al1, al2, al3, bh0, bh1);
            }
        }
        // ---- softmax phase A: warp-local row max over 32 keys
        float m0 = fmaxf(fmaxf(sacc[0][0], sacc[0][1]), fmaxf(sacc[1][0], sacc[1][1]));
        m0 = fmaxf(m0, fmaxf(fmaxf(sacc[2][0], sacc[2][1]), fmaxf(sacc[3][0], sacc[3][1])));
        float m1 = fmaxf(fmaxf(sacc[0][2], sacc[0][3]), fmaxf(sacc[1][2], sacc[1][3]));
        m1 = fmaxf(m1, fmaxf(fmaxf(sacc[2][2], sacc[2][3]), fmaxf(sacc[3][2], sacc[3][3])));
        m0 = fmaxf(m0, __shfl_xor_sync(0xffffffffu, m0, 1));
        m0 = fmaxf(m0, __shfl_xor_sync(0xffffffffu, m0, 2));
        m1 = fmaxf(m1, __shfl_xor_sync(0xffffffffu, m1, 1));
        m1 = fmaxf(m1, __shfl_xor_sync(0xffffffffu, m1, 2));
        float rm0 = rmax[rowg], rm1 = rmax[rowg + 8];
        if (t == 0) {
            wmax[ntk * 64 + rowg]     = m0;
            wmax[ntk * 64 + rowg + 8] = m1;
        }
        __syncthreads();                       // C: wmax visible
        // ---- softmax phase B: exp in registers, pack to Ps16
        float nm0 = fmaxf(rm0, fmaxf(wmax[rowg], wmax[64 + rowg]));
        float nm1 = fmaxf(rm1, fmaxf(wmax[rowg + 8], wmax[64 + rowg + 8]));
        float s0 = 0.f, s1 = 0.f;
#pragma unroll
        for (int sub = 0; sub < 4; sub++) {
            float p00 = __expf(sacc[sub][0] - nm0);
            float p01 = __expf(sacc[sub][1] - nm0);
            float p10 = __expf(sacc[sub][2] - nm1);
            float p11 = __expf(sacc[sub][3] - nm1);
            s0 += p00 + p01; s1 += p10 + p11;
            int kp = ntk * 16 + sub * 4 + t;
            Ps16[rowg * 36 + kp]       = pack2(p00, p01);
            Ps16[(rowg + 8) * 36 + kp] = pack2(p10, p11);
        }
        s0 += __shfl_xor_sync(0xffffffffu, s0, 1);
        s0 += __shfl_xor_sync(0xffffffffu, s0, 2);
        s1 += __shfl_xor_sync(0xffffffffu, s1, 1);
        s1 += __shfl_xor_sync(0xffffffffu, s1, 2);
        if (t == 0) {
            wsum[ntk * 64 + rowg]     = s0;
            wsum[ntk * 64 + rowg + 8] = s1;
            if (ntk == 0) {
                rscale[rowg]     = __expf(rm0 - nm0);
                rscale[rowg + 8] = __expf(rm1 - nm1);
                rmax[rowg] = nm0; rmax[rowg + 8] = nm1;
            }
        }
        __syncthreads();                       // D: Ps16 + rscale + wsum visible
        // ---- PV: rescale + fp16 MMA (warp: 32 rows x 64 ch, 64 keys)
        {
#pragma unroll
            for (int rt = 0; rt < 2; rt++) {
                float sc0 = rscale[wm * 32 + rt * 16 + g];
                float sc1 = rscale[wm * 32 + rt * 16 + g + 8];
#pragma unroll
                for (int nt = 0; nt < 8; nt++) {
                    acc[rt][nt][0] *= sc0; acc[rt][nt][1] *= sc0;
                    acc[rt][nt][2] *= sc1; acc[rt][nt][3] *= sc1;
                }
            }
#pragma unroll
            for (int kt = 0; kt < 4; kt++) {
                u32 pa[2][4];
#pragma unroll
                for (int rt = 0; rt < 2; rt++) {
                    int pr = (wm * 32 + rt * 16 + g) * 36 + kt * 8 + t;
                    pa[rt][0] = Ps16[pr];       pa[rt][1] = Ps16[pr + 288];
                    pa[rt][2] = Ps16[pr + 4];   pa[rt][3] = Ps16[pr + 292];
                }
#pragma unroll
                for (int nt = 0; nt < 8; nt++) {
                    int vr = (wslab + nt * 8 + g) * 36 + kt * 8 + t;
                    u32 b0 = Vs[vr], b1 = Vs[vr + 4];   // loaded once, used twice
                    MMA_F16(acc[0][nt], pa[0][0], pa[0][1], pa[0][2], pa[0][3], b0, b1);
                    MMA_F16(acc[1][nt], pa[1][0], pa[1][1], pa[1][2], pa[1][3], b0, b1);
                }
            }
        }
        // running-sum update (rsum read only at epilogue)
        if (w < 4 && lane < 16) {
            int row = w * 16 + lane;
            rsum[row] = rsum[row] * rscale[row] + wsum[row] + wsum[64 + row];
        }
    }
    // epilogue: two passes of 32 rows staged, then coalesced write/RMW
    float gm = 0.5f * gamma[0];
#pragma unroll
    for (int pass = 0; pass < 2; pass++) {
        __syncthreads();
        if (wm == pass) {
#pragma unroll
            for (int rt = 0; rt < 2; rt++) {
                float f0 = gm / rsum[wm * 32 + rt * 16 + g];
                float f1 = gm / rsum[wm * 32 + rt * 16 + g + 8];
                int row0 = rt * 16 + g;
                int r0 = row0 * 264 + wslab + 2 * t;
                int r8 = (row0 + 8) * 264 + wslab + 2 * t;
#pragma unroll
                for (int nt = 0; nt < 8; nt++) {
                    stage[r0 + nt * 8]     = acc[rt][nt][0] * f0;
                    stage[r0 + nt * 8 + 1] = acc[rt][nt][1] * f0;
                    stage[r8 + nt * 8]     = acc[rt][nt][2] * f1;
                    stage[r8 + nt * 8 + 1] = acc[rt][nt][3] * f1;
                }
            }
        }
        __syncthreads();
        int tn = tid & 7, tc = tid >> 3;
#pragma unroll
        for (int i = 0; i < 4; i++) {
            int row = tn + 8 * i;
            int pa = pas[pass * 32 + row];
#pragma unroll
            for (int j = 0; j < 8; j++) {
                int c = tc * 8 + j;
                float vv = stage[row * 264 + c];
                if (mode) out[pa + c * HW] += vv;
                else      out[pa + c * HW] = xin[pa + c * HW] + vv;
            }
        }
    }
}

// ---------------------------------------------------------------- launcher
extern "C" void kernel_launch(void* const* d_in, const int* in_sizes, int n_in,
                              void* d_out, int out_size) {
    const float* x   = (const float*)d_in[0];
    const float* Wq  = (const float*)d_in[1];
    const float* bq  = (const float*)d_in[2];
    const float* q_s = (const float*)d_in[3];
    const float* q_o = (const float*)d_in[4];
    const float* q_m = (const float*)d_in[5];
    const float* q_v = (const float*)d_in[6];
    const float* Wk  = (const float*)d_in[7];
    const float* bk  = (const float*)d_in[8];
    const float* k_s = (const float*)d_in[9];
    const float* k_o = (const float*)d_in[10];
    const float* k_m = (const float*)d_in[11];
    const float* k_v = (const float*)d_in[12];
    const float* Wv  = (const float*)d_in[13];
    const float* bv  = (const float*)d_in[14];
    const float* gam = (const float*)d_in[15];
    float* out = (float*)d_out;

    cudaFuncSetAttribute(attn, cudaFuncAttributeMaxDynamicSharedMemorySize, ASMEM);

    prep_wall<<<224, 256>>>(Wq, Wk, Wv);
    prep_bn<<<1, 32>>>(bq, q_s, q_o, q_m, q_v, bk, k_s, k_o, k_m, k_v);
    prep_pix<<<dim3(6, 232), 256>>>();
    x_pack<<<TOTPIX / 32, 256>>>(x);
    qkv_gemm<<<dim3(7, 24, 232), 256, QSMEM>>>(bv);
    combine_qk<<<dim3(96, 232), 256>>>();
    // shift regions (12..28) partition the image: write mode (out = x + delta)
    attn<<<dim3(24, 136), 256, ASMEM>>>(gam, x, out, 96, 0);
    // win regions (0..11): disjoint pixels within launch -> RMW
    attn<<<dim3(16, 96), 256, ASMEM>>>(gam, x, out, 0, 1);
}